// round 1
// baseline (speedup 1.0000x reference)
#include <cuda_runtime.h>
#include <math_constants.h>
#include <cstdio>

// Problem sizes (fixed by the dataset)
#define BB 64
#define LL 512
#define DD 512
#define AA 256

// Scratch (allowed: __device__ globals, no allocation at runtime)
__device__ float g_T [(size_t)BB * LL * DD];   // S1 @ W          [B,L1,D]
__device__ float g_P [(size_t)BB * LL * AA];   // S1 @ Wv         [B,L1,A]
__device__ float g_Q [(size_t)BB * LL * AA];   // S2 @ Wq         [B,L2,A]
__device__ float g_C [(size_t)BB * LL * LL];   // tanh(T @ S2^T)  [B,L1,L2]
__device__ float g_Hv[(size_t)BB * LL * AA];   // tanh(P + C@Q)
__device__ float g_Hq[(size_t)BB * LL * AA];   // tanh(Q + C^T@P)

// ---------------------------------------------------------------------------
// Generic tiled SGEMM: out[M,N] = opA(A) @ opB(B) (+bias) (tanh)
//   OPA=0: A row-major [M,K]; OPA=1: A row-major [K,M] (transposed access)
//   OPB=0: B row-major [K,N]; OPB=1: B row-major [N,K] (i.e. A@B^T)
//   EPI=0: plain; EPI=1: tanh(out); EPI=2: tanh(out + bias) (bias same shape)
// Tile 128x128xBK16, 256 threads, 8x8 per-thread microtile.
// All dims assumed multiples of 128 (true here). Batched via blockIdx.z.
// ---------------------------------------------------------------------------
template<int OPA, int OPB, int EPI>
__global__ void __launch_bounds__(256, 2)
sgemm_k(const float* __restrict__ A, size_t sA, int lda,
        const float* __restrict__ B, size_t sB, int ldb,
        const float* __restrict__ bias, size_t sBias,
        float* __restrict__ Cout, size_t sC, int ldc,
        int K)
{
    __shared__ float As[16][128];
    __shared__ float Bs[16][128];

    const int z = blockIdx.z;
    A    += (size_t)z * sA;
    B    += (size_t)z * sB;
    Cout += (size_t)z * sC;
    if (EPI == 2) bias += (size_t)z * sBias;

    const int bm = blockIdx.y * 128;
    const int bn = blockIdx.x * 128;
    const int tid = threadIdx.x;
    const int tx = tid & 15;      // 0..15 -> N microtile
    const int ty = tid >> 4;      // 0..15 -> M microtile

    float acc[8][8];
    #pragma unroll
    for (int i = 0; i < 8; i++)
        #pragma unroll
        for (int j = 0; j < 8; j++) acc[i][j] = 0.f;

    for (int kk = 0; kk < K; kk += 16) {
        // ---- load A tile into As[k][m] ----
        if (OPA == 0) {
            int r = tid >> 2;              // 0..63 (row within tile)
            int c = (tid & 3) << 2;        // 0,4,8,12 (k offset)
            const float* p = A + (size_t)(bm + r) * lda + kk + c;
            float4 v0 = *(const float4*)p;
            float4 v1 = *(const float4*)(p + (size_t)64 * lda);
            As[c + 0][r] = v0.x; As[c + 1][r] = v0.y;
            As[c + 2][r] = v0.z; As[c + 3][r] = v0.w;
            As[c + 0][r + 64] = v1.x; As[c + 1][r + 64] = v1.y;
            As[c + 2][r + 64] = v1.z; As[c + 3][r + 64] = v1.w;
        } else {
            int r = tid >> 5;              // 0..7 (k row)
            int c = (tid & 31) << 2;       // 0..124 (m col)
            const float* p = A + (size_t)(kk + r) * lda + bm + c;
            *(float4*)&As[r][c]     = *(const float4*)p;
            *(float4*)&As[r + 8][c] = *(const float4*)(p + (size_t)8 * lda);
        }
        // ---- load B tile into Bs[k][n] ----
        if (OPB == 0) {
            int r = tid >> 5;
            int c = (tid & 31) << 2;
            const float* p = B + (size_t)(kk + r) * ldb + bn + c;
            *(float4*)&Bs[r][c]     = *(const float4*)p;
            *(float4*)&Bs[r + 8][c] = *(const float4*)(p + (size_t)8 * ldb);
        } else {
            int r = tid >> 2;              // n row within tile
            int c = (tid & 3) << 2;        // k offset
            const float* p = B + (size_t)(bn + r) * ldb + kk + c;
            float4 v0 = *(const float4*)p;
            float4 v1 = *(const float4*)(p + (size_t)64 * ldb);
            Bs[c + 0][r] = v0.x; Bs[c + 1][r] = v0.y;
            Bs[c + 2][r] = v0.z; Bs[c + 3][r] = v0.w;
            Bs[c + 0][r + 64] = v1.x; Bs[c + 1][r + 64] = v1.y;
            Bs[c + 2][r + 64] = v1.z; Bs[c + 3][r + 64] = v1.w;
        }
        __syncthreads();

        #pragma unroll
        for (int k = 0; k < 16; k++) {
            float a[8], b[8];
            *(float4*)(a)     = *(const float4*)&As[k][ty * 8];
            *(float4*)(a + 4) = *(const float4*)&As[k][ty * 8 + 4];
            *(float4*)(b)     = *(const float4*)&Bs[k][tx * 8];
            *(float4*)(b + 4) = *(const float4*)&Bs[k][tx * 8 + 4];
            #pragma unroll
            for (int i = 0; i < 8; i++)
                #pragma unroll
                for (int j = 0; j < 8; j++)
                    acc[i][j] = fmaf(a[i], b[j], acc[i][j]);
        }
        __syncthreads();
    }

    // ---- epilogue ----
    #pragma unroll
    for (int i = 0; i < 8; i++) {
        int row = bm + ty * 8 + i;
        float* cp = Cout + (size_t)row * ldc + bn + tx * 8;
        const float* bp = (EPI == 2) ? (bias + (size_t)row * ldc + bn + tx * 8) : nullptr;
        #pragma unroll
        for (int j = 0; j < 8; j += 4) {
            float4 v;
            v.x = acc[i][j]; v.y = acc[i][j + 1];
            v.z = acc[i][j + 2]; v.w = acc[i][j + 3];
            if (EPI == 2) {
                float4 bv = *(const float4*)(bp + j);
                v.x += bv.x; v.y += bv.y; v.z += bv.z; v.w += bv.w;
            }
            if (EPI >= 1) {
                v.x = tanhf(v.x); v.y = tanhf(v.y);
                v.z = tanhf(v.z); v.w = tanhf(v.w);
            }
            *(float4*)(cp + j) = v;
        }
    }
}

// ---------------------------------------------------------------------------
// Per-batch: logits = H @ w; masked softmax (faithful to ref); out = attn @ X
// One CTA per batch, 256 threads (8 warps).
// ---------------------------------------------------------------------------
__device__ __forceinline__ float block_sum(float v, float* red)
{
    int lane = threadIdx.x & 31, warp = threadIdx.x >> 5;
    #pragma unroll
    for (int o = 16; o; o >>= 1) v += __shfl_xor_sync(0xffffffffu, v, o);
    if (lane == 0) red[warp] = v;
    __syncthreads();
    float t = 0.f;
    #pragma unroll
    for (int i = 0; i < 8; i++) t += red[i];
    __syncthreads();
    return t;
}

__device__ __forceinline__ float block_max(float v, float* red)
{
    int lane = threadIdx.x & 31, warp = threadIdx.x >> 5;
    #pragma unroll
    for (int o = 16; o; o >>= 1) v = fmaxf(v, __shfl_xor_sync(0xffffffffu, v, o));
    if (lane == 0) red[warp] = v;
    __syncthreads();
    float t = red[0];
    #pragma unroll
    for (int i = 1; i < 8; i++) t = fmaxf(t, red[i]);
    __syncthreads();
    return t;
}

__global__ void __launch_bounds__(256)
attn_pool_k(const float* __restrict__ H,   // [B,L,A]
            const float* __restrict__ w,   // [A]
            const int*   __restrict__ mask,// [B,L]
            const float* __restrict__ X,   // [B,L,D]
            float* __restrict__ out)       // [B,D]
{
    __shared__ float sw[AA];
    __shared__ float sl[LL];
    __shared__ float smk[LL];
    __shared__ float red[8];

    const int b = blockIdx.x;
    const int tid = threadIdx.x;
    const int lane = tid & 31, warp = tid >> 5;

    for (int a = tid; a < AA; a += 256) sw[a] = w[a];
    for (int l = tid; l < LL; l += 256) smk[l] = (float)mask[b * LL + l];
    __syncthreads();

    // logits (warp per row, coalesced over A)
    for (int l = warp; l < LL; l += 8) {
        const float* Hr = H + ((size_t)b * LL + l) * AA;
        float s = 0.f;
        #pragma unroll
        for (int a = lane; a < AA; a += 32) s = fmaf(Hr[a], sw[a], s);
        #pragma unroll
        for (int o = 16; o; o >>= 1) s += __shfl_down_sync(0xffffffffu, s, o);
        if (lane == 0) sl[l] = s * smk[l];   // v * mask (pre-softmax)
    }
    __syncthreads();

    // softmax(v*mask)
    float m = -CUDART_INF_F;
    for (int l = tid; l < LL; l += 256) m = fmaxf(m, sl[l]);
    m = block_max(m, red);

    float psum = 0.f;
    for (int l = tid; l < LL; l += 256) {
        float e = expf(sl[l] - m);
        sl[l] = e;
        psum += e;
    }
    psum = block_sum(psum, red);
    float inv = 1.f / psum;

    // re-mask + renormalize with eps (faithful)
    float rsum = 0.f;
    for (int l = tid; l < LL; l += 256) {
        float r = sl[l] * inv * smk[l];
        sl[l] = r;
        rsum += r;
    }
    rsum = block_sum(rsum, red);
    float sc = 1.f / (rsum + 1e-13f);
    for (int l = tid; l < LL; l += 256) sl[l] *= sc;
    __syncthreads();

    // pooled output: out[b,d] = sum_l attn[l] * X[b,l,d]
    for (int d = tid; d < DD; d += 256) {
        const float* Xb = X + (size_t)b * LL * DD + d;
        float acc = 0.f;
        #pragma unroll 4
        for (int l = 0; l < LL; l++) acc = fmaf(sl[l], Xb[(size_t)l * DD], acc);
        out[(size_t)b * DD + d] = acc;
    }
}

// ---------------------------------------------------------------------------
extern "C" void kernel_launch(void* const* d_in, const int* in_sizes, int n_in,
                              void* d_out, int out_size)
{
    const float* S1   = (const float*)d_in[0];   // [B,L1,D]
    const float* S2   = (const float*)d_in[1];   // [B,L2,D]
    const int*   mask1= (const int*)  d_in[2];   // [B,L1]
    const int*   mask2= (const int*)  d_in[3];   // [B,L2]
    const float* W    = (const float*)d_in[4];   // [D,D]
    const float* Wv   = (const float*)d_in[5];   // [D,A]
    const float* Wq   = (const float*)d_in[6];   // [D,A]
    const float* w_hv = (const float*)d_in[7];   // [A,1]
    const float* w_hq = (const float*)d_in[8];   // [A,1]
    float* out = (float*)d_out;                  // [B,D] ++ [B,D]

    float *T, *P, *Q, *C, *Hv, *Hq;
    cudaGetSymbolAddress((void**)&T,  g_T);
    cudaGetSymbolAddress((void**)&P,  g_P);
    cudaGetSymbolAddress((void**)&Q,  g_Q);
    cudaGetSymbolAddress((void**)&C,  g_C);
    cudaGetSymbolAddress((void**)&Hv, g_Hv);
    cudaGetSymbolAddress((void**)&Hq, g_Hq);

    const dim3 blk(256);
    const size_t sLD = (size_t)LL * DD;   // per-batch stride of [L,D]
    const size_t sLA = (size_t)LL * AA;   // per-batch stride of [L,A]
    const size_t sLL = (size_t)LL * LL;   // per-batch stride of [L,L]

    // 1) T = S1f @ W       [B*L, D] @ [D, D]
    sgemm_k<0,0,0><<<dim3(DD/128, (BB*LL)/128, 1), blk>>>(
        S1, 0, DD,  W, 0, DD,  nullptr, 0,  T, 0, DD,  DD);
    // 2) P = S1f @ Wv      [B*L, D] @ [D, A]
    sgemm_k<0,0,0><<<dim3(AA/128, (BB*LL)/128, 1), blk>>>(
        S1, 0, DD,  Wv, 0, AA,  nullptr, 0,  P, 0, AA,  DD);
    // 3) Q = S2f @ Wq
    sgemm_k<0,0,0><<<dim3(AA/128, (BB*LL)/128, 1), blk>>>(
        S2, 0, DD,  Wq, 0, AA,  nullptr, 0,  Q, 0, AA,  DD);
    // 4) C_b = tanh(T_b @ S2_b^T)   (batched NT)
    sgemm_k<0,1,1><<<dim3(LL/128, LL/128, BB), blk>>>(
        T, sLD, DD,  S2, sLD, DD,  nullptr, 0,  C, sLL, LL,  DD);
    // 5) Hv_b = tanh(P_b + C_b @ Q_b)   (batched NN + bias + tanh)
    sgemm_k<0,0,2><<<dim3(AA/128, LL/128, BB), blk>>>(
        C, sLL, LL,  Q, sLA, AA,  P, sLA,  Hv, sLA, AA,  LL);
    // 6) Hq_b = tanh(Q_b + C_b^T @ P_b) (batched TN + bias + tanh)
    sgemm_k<1,0,2><<<dim3(AA/128, LL/128, BB), blk>>>(
        C, sLL, LL,  P, sLA, AA,  Q, sLA,  Hq, sLA, AA,  LL);
    // 7) attn_v -> v_hat ; 8) attn_q -> q_hat
    attn_pool_k<<<BB, blk>>>(Hv, w_hv, mask1, S1, out);
    attn_pool_k<<<BB, blk>>>(Hq, w_hq, mask2, S2, out + (size_t)BB * DD);
}

// round 3
// speedup vs baseline: 1.2141x; 1.2141x over previous
#include <cuda_runtime.h>
#include <cuda_bf16.h>
#include <math_constants.h>
#include <cstdint>

#define BBATCH 64
#define LLEN   512
#define DDIM   512
#define AADIM  256
#define BL     (BBATCH * LLEN)   // 32768

// ---------------- scratch (__device__ globals) -------------------------------
__device__ __align__(256) __nv_bfloat16 g_S1h[(size_t)BL * DDIM];
__device__ __align__(256) __nv_bfloat16 g_S1l[(size_t)BL * DDIM];
__device__ __align__(256) __nv_bfloat16 g_S2h[(size_t)BL * DDIM];
__device__ __align__(256) __nv_bfloat16 g_S2l[(size_t)BL * DDIM];
__device__ __align__(256) __nv_bfloat16 g_Wth[(size_t)DDIM * DDIM];
__device__ __align__(256) __nv_bfloat16 g_Wtl[(size_t)DDIM * DDIM];
__device__ __align__(256) __nv_bfloat16 g_Wvth[(size_t)AADIM * DDIM];
__device__ __align__(256) __nv_bfloat16 g_Wvtl[(size_t)AADIM * DDIM];
__device__ __align__(256) __nv_bfloat16 g_Wqth[(size_t)AADIM * DDIM];
__device__ __align__(256) __nv_bfloat16 g_Wqtl[(size_t)AADIM * DDIM];
__device__ __align__(256) __nv_bfloat16 g_Th [(size_t)BL * DDIM];
__device__ __align__(256) __nv_bfloat16 g_Tl [(size_t)BL * DDIM];
__device__ __align__(256) __nv_bfloat16 g_Ch [(size_t)BBATCH * LLEN * LLEN];
__device__ __align__(256) __nv_bfloat16 g_Cl [(size_t)BBATCH * LLEN * LLEN];
__device__ __align__(256) __nv_bfloat16 g_CTh[(size_t)BBATCH * LLEN * LLEN];
__device__ __align__(256) __nv_bfloat16 g_CTl[(size_t)BBATCH * LLEN * LLEN];
__device__ __align__(256) __nv_bfloat16 g_Pth[(size_t)AADIM * BL];
__device__ __align__(256) __nv_bfloat16 g_Ptl[(size_t)AADIM * BL];
__device__ __align__(256) __nv_bfloat16 g_Qth[(size_t)AADIM * BL];
__device__ __align__(256) __nv_bfloat16 g_Qtl[(size_t)AADIM * BL];
__device__ __align__(256) float g_P [(size_t)BL * AADIM];
__device__ __align__(256) float g_Q [(size_t)BL * AADIM];
__device__ __align__(256) float g_Hv[(size_t)BL * AADIM];
__device__ __align__(256) float g_Hq[(size_t)BL * AADIM];

// ---------------- helpers -----------------------------------------------------
__device__ __forceinline__ uint32_t smem_u32(const void* p) {
    uint32_t a;
    asm("{ .reg .u64 t; cvta.to.shared.u64 t, %1; cvt.u32.u64 %0, t; }"
        : "=r"(a) : "l"(p));
    return a;
}
__device__ __forceinline__ uint32_t pk(__nv_bfloat16 a, __nv_bfloat16 b) {
    __nv_bfloat162 t = __halves2bfloat162(a, b);
    return *reinterpret_cast<uint32_t*>(&t);
}
__device__ __forceinline__ void split_f(float x, __nv_bfloat16& h, __nv_bfloat16& l) {
    h = __float2bfloat16(x);
    l = __float2bfloat16(x - __bfloat162float(h));
}

#define CP16(SM, G) \
    asm volatile("cp.async.cg.shared.global [%0], [%1], 16;" :: "r"(SM), "l"(G))
#define CP_COMMIT() asm volatile("cp.async.commit_group;")
#define CP_WAIT1()  asm volatile("cp.async.wait_group 1;")
#define CP_WAIT0()  asm volatile("cp.async.wait_group 0;")

#define LDSM4(R0,R1,R2,R3,ADDR) \
    asm volatile("ldmatrix.sync.aligned.m8n8.x4.shared.b16 {%0,%1,%2,%3}, [%4];" \
        : "=r"(R0),"=r"(R1),"=r"(R2),"=r"(R3) : "r"(ADDR))

__device__ __forceinline__ void mma_bf16(float* d, const uint32_t* a, const uint32_t* b) {
    asm volatile(
        "mma.sync.aligned.m16n8k16.row.col.f32.bf16.bf16.f32 "
        "{%0,%1,%2,%3}, {%4,%5,%6,%7}, {%8,%9}, {%0,%1,%2,%3};"
        : "+f"(d[0]), "+f"(d[1]), "+f"(d[2]), "+f"(d[3])
        : "r"(a[0]), "r"(a[1]), "r"(a[2]), "r"(a[3]), "r"(b[0]), "r"(b[1]));
}

// stage layout: AH 0 | AL 16K | BH 32K | BL 48K ; two stages of 64KB
#define STG 65536
#define SM_BYTES 131072

// one bf16 array tile: 128 rows x 64 k-elems (128B/row), SW128 xor swizzle
__device__ __forceinline__ void stage_arr(uint32_t sdst, const __nv_bfloat16* src,
                                          int rowbase, int ld, int kc, int tid)
{
    #pragma unroll
    for (int q = 0; q < 4; q++) {
        int idx = tid + q * 256;
        int r = idx >> 3, c = idx & 7;
        uint32_t sa = sdst + r * 128 + ((c ^ (r & 7)) << 4);
        const __nv_bfloat16* g = src + (size_t)(rowbase + r) * ld + kc * 64 + c * 8;
        CP16(sa, g);
    }
}

// ---------------- main MMA GEMM ------------------------------------------------
// out[i][j] = sum_k A[i][k]*B[j][k]  (A,B: bf16 hi/lo, K-major, K=512)
// EPI 0: store bf16 hi/lo natural [i][j]                          (T)
// EPI 1: EPI0 + bounce-transposed fp32 [j][i]                     (Pt/P, Qt/Q)
// EPI 2: tanh; bf16 hi/lo natural [i][j] + bounce bf16 [j][i]     (C, CT)
// EPI 3: tanh(acc + bias[i][j]); fp32 natural [i][j]              (Hv, Hq)
template<int EPI>
__global__ void __launch_bounds__(256, 1)
gemm_mma(const __nv_bfloat16* __restrict__ Ah, const __nv_bfloat16* __restrict__ Al,
         size_t sA, int ldA,
         const __nv_bfloat16* __restrict__ Bh2, const __nv_bfloat16* __restrict__ Bl2,
         size_t sB, int ldB,
         const float* __restrict__ bias, size_t sBias, int ldBias,
         float* __restrict__ outF, size_t sF, int ldF,
         __nv_bfloat16* __restrict__ oh, __nv_bfloat16* __restrict__ ol,
         size_t sO, int ldO,
         __nv_bfloat16* __restrict__ th, __nv_bfloat16* __restrict__ tl,
         size_t sT, int ldT)
{
    extern __shared__ char smem[];
    const int tid  = threadIdx.x;
    const int lane = tid & 31, warp = tid >> 5;
    const int wm = warp >> 2, wn = warp & 3;   // 2 x 4 warp grid
    const int z  = blockIdx.z;
    const int bi = blockIdx.x * 128, bj = blockIdx.y * 128;

    Ah  += (size_t)z * sA;  Al  += (size_t)z * sA;
    Bh2 += (size_t)z * sB;  Bl2 += (size_t)z * sB;
    if (EPI == 3) bias += (size_t)z * sBias;
    if (outF) outF += (size_t)z * sF;
    if (oh)   { oh += (size_t)z * sO; ol += (size_t)z * sO; }
    if (th)   { th += (size_t)z * sT; tl += (size_t)z * sT; }

    const uint32_t su = smem_u32(smem);

    float acc[4][4][4];
    #pragma unroll
    for (int a = 0; a < 4; a++)
        #pragma unroll
        for (int b = 0; b < 4; b++)
            #pragma unroll
            for (int c = 0; c < 4; c++) acc[a][b][c] = 0.f;

    // lane-derived ldmatrix row/chunk parts
    const int arow_lo   = lane & 15;
    const int achunk_ad = lane >> 4;
    const int gB        = lane >> 3;
    const int brow_lo   = ((gB >> 1) << 3) + (lane & 7);
    const int bchunk_ad = gB & 1;

    // prologue: stage chunk 0
    {
        uint32_t sb = su;
        stage_arr(sb,          Ah,  bi, ldA, 0, tid);
        stage_arr(sb + 16384,  Al,  bi, ldA, 0, tid);
        stage_arr(sb + 32768,  Bh2, bj, ldB, 0, tid);
        stage_arr(sb + 49152,  Bl2, bj, ldB, 0, tid);
        CP_COMMIT();
    }

    #pragma unroll 1
    for (int c = 0; c < 8; c++) {
        if (c < 7) {
            uint32_t sb = su + ((c + 1) & 1) * STG;
            stage_arr(sb,         Ah,  bi, ldA, c + 1, tid);
            stage_arr(sb + 16384, Al,  bi, ldA, c + 1, tid);
            stage_arr(sb + 32768, Bh2, bj, ldB, c + 1, tid);
            stage_arr(sb + 49152, Bl2, bj, ldB, c + 1, tid);
            CP_COMMIT();
            CP_WAIT1();
        } else {
            CP_WAIT0();
        }
        __syncthreads();

        const uint32_t aB  = su + (c & 1) * STG;
        const uint32_t alB = aB + 16384;
        const uint32_t bB  = aB + 32768;
        const uint32_t blB = aB + 49152;

        #pragma unroll
        for (int kb = 0; kb < 4; kb++) {
            uint32_t ah[4][4], al[4][4], bh[4][2], bl[4][2];
            #pragma unroll
            for (int mi = 0; mi < 4; mi++) {
                int row = wm * 64 + mi * 16 + arow_lo;
                int ch  = (kb * 2 + achunk_ad) ^ (row & 7);
                uint32_t off = row * 128 + (ch << 4);
                LDSM4(ah[mi][0], ah[mi][1], ah[mi][2], ah[mi][3], aB  + off);
                LDSM4(al[mi][0], al[mi][1], al[mi][2], al[mi][3], alB + off);
            }
            #pragma unroll
            for (int ng = 0; ng < 2; ng++) {
                int row = wn * 32 + ng * 16 + brow_lo;
                int ch  = (kb * 2 + bchunk_ad) ^ (row & 7);
                uint32_t off = row * 128 + (ch << 4);
                uint32_t t0, t1, t2, t3;
                LDSM4(t0, t1, t2, t3, bB + off);
                bh[ng*2][0] = t0; bh[ng*2][1] = t1; bh[ng*2+1][0] = t2; bh[ng*2+1][1] = t3;
                LDSM4(t0, t1, t2, t3, blB + off);
                bl[ng*2][0] = t0; bl[ng*2][1] = t1; bl[ng*2+1][0] = t2; bl[ng*2+1][1] = t3;
            }
            #pragma unroll
            for (int mi = 0; mi < 4; mi++)
                #pragma unroll
                for (int ni = 0; ni < 4; ni++) {
                    mma_bf16(acc[mi][ni], ah[mi], bh[ni]);
                    mma_bf16(acc[mi][ni], ah[mi], bl[ni]);
                    mma_bf16(acc[mi][ni], al[mi], bh[ni]);
                }
        }
        __syncthreads();
    }

    // ---------------- epilogue ----------------
    const int trow = lane >> 2;
    const int tcol = (lane & 3) * 2;

    if (EPI == 2) {   // tanh in place
        #pragma unroll
        for (int mi = 0; mi < 4; mi++)
            #pragma unroll
            for (int ni = 0; ni < 4; ni++)
                #pragma unroll
                for (int q = 0; q < 4; q++)
                    acc[mi][ni][q] = tanhf(acc[mi][ni][q]);
    }

    if (EPI == 0 || EPI == 1 || EPI == 2) {   // natural bf16 hi/lo stores
        #pragma unroll
        for (int mi = 0; mi < 4; mi++)
            #pragma unroll
            for (int ni = 0; ni < 4; ni++) {
                int j = bj + wn * 32 + ni * 8 + tcol;
                #pragma unroll
                for (int hf = 0; hf < 2; hf++) {
                    int i = bi + wm * 64 + mi * 16 + trow + hf * 8;
                    float v0 = acc[mi][ni][hf * 2 + 0];
                    float v1 = acc[mi][ni][hf * 2 + 1];
                    __nv_bfloat16 h0, l0, h1, l1;
                    split_f(v0, h0, l0); split_f(v1, h1, l1);
                    *(uint32_t*)&oh[(size_t)i * ldO + j] = pk(h0, h1);
                    *(uint32_t*)&ol[(size_t)i * ldO + j] = pk(l0, l1);
                }
            }
    }

    if (EPI == 1 || EPI == 2) {   // bounce transpose via smem (pitch 129 f32)
        float* smf = (float*)smem;
        #pragma unroll
        for (int mi = 0; mi < 4; mi++)
            #pragma unroll
            for (int ni = 0; ni < 4; ni++) {
                int jl = wn * 32 + ni * 8 + tcol;
                #pragma unroll
                for (int hf = 0; hf < 2; hf++) {
                    int il = wm * 64 + mi * 16 + trow + hf * 8;
                    smf[il * 129 + jl]     = acc[mi][ni][hf * 2 + 0];
                    smf[il * 129 + jl + 1] = acc[mi][ni][hf * 2 + 1];
                }
            }
        __syncthreads();
        int r2 = tid >> 1, hf2 = tid & 1;
        if (EPI == 1) {
            #pragma unroll 8
            for (int cc = 0; cc < 64; cc++) {
                int col = hf2 * 64 + cc;
                outF[(size_t)(bj + r2) * ldF + bi + col] = smf[col * 129 + r2];
            }
        } else {
            #pragma unroll 4
            for (int cc = 0; cc < 64; cc += 2) {
                int col = hf2 * 64 + cc;
                float v0 = smf[col * 129 + r2];
                float v1 = smf[(col + 1) * 129 + r2];
                __nv_bfloat16 h0, l0, h1, l1;
                split_f(v0, h0, l0); split_f(v1, h1, l1);
                *(uint32_t*)&th[(size_t)(bj + r2) * ldT + bi + col] = pk(h0, h1);
                *(uint32_t*)&tl[(size_t)(bj + r2) * ldT + bi + col] = pk(l0, l1);
            }
        }
    }

    if (EPI == 3) {
        #pragma unroll
        for (int mi = 0; mi < 4; mi++)
            #pragma unroll
            for (int ni = 0; ni < 4; ni++) {
                int j = bj + wn * 32 + ni * 8 + tcol;
                #pragma unroll
                for (int hf = 0; hf < 2; hf++) {
                    int i = bi + wm * 64 + mi * 16 + trow + hf * 8;
                    float2 bv = *(const float2*)&bias[(size_t)i * ldBias + j];
                    float2 o;
                    o.x = tanhf(acc[mi][ni][hf * 2 + 0] + bv.x);
                    o.y = tanhf(acc[mi][ni][hf * 2 + 1] + bv.y);
                    *(float2*)&outF[(size_t)i * ldF + j] = o;
                }
            }
    }
}

// ---------------- prep: fp32 -> bf16 hi/lo split ------------------------------
__global__ void __launch_bounds__(256)
split_k(const float4* __restrict__ in, uint2* __restrict__ hi, uint2* __restrict__ lo, int n4)
{
    int i = blockIdx.x * 256 + threadIdx.x;
    if (i >= n4) return;
    float4 v = in[i];
    __nv_bfloat16 h0,h1,h2,h3,l0,l1,l2,l3;
    split_f(v.x,h0,l0); split_f(v.y,h1,l1); split_f(v.z,h2,l2); split_f(v.w,h3,l3);
    hi[i] = make_uint2(pk(h0,h1), pk(h2,h3));
    lo[i] = make_uint2(pk(l0,l1), pk(l2,l3));
}

// transpose [R][C] fp32 -> [C][R] bf16 hi/lo
__global__ void __launch_bounds__(256)
tsplit_k(const float* __restrict__ in, int R, int C,
         __nv_bfloat16* __restrict__ oh, __nv_bfloat16* __restrict__ ol)
{
    __shared__ float t[32][33];
    int bx = blockIdx.x * 32, by = blockIdx.y * 32;
    int tx = threadIdx.x & 31, ty = threadIdx.x >> 5;   // 32 x 8
    #pragma unroll
    for (int i = 0; i < 32; i += 8)
        t[ty + i][tx] = in[(size_t)(by + ty + i) * C + bx + tx];
    __syncthreads();
    #pragma unroll
    for (int i = 0; i < 32; i += 8) {
        float v = t[tx][ty + i];
        __nv_bfloat16 h, l; split_f(v, h, l);
        oh[(size_t)(bx + ty + i) * R + by + tx] = h;
        ol[(size_t)(bx + ty + i) * R + by + tx] = l;
    }
}

// ---------------- masked softmax + pooling (R1, unchanged) --------------------
__device__ __forceinline__ float block_sum(float v, float* red) {
    int lane = threadIdx.x & 31, warp = threadIdx.x >> 5;
    #pragma unroll
    for (int o = 16; o; o >>= 1) v += __shfl_xor_sync(0xffffffffu, v, o);
    if (lane == 0) red[warp] = v;
    __syncthreads();
    float t = 0.f;
    #pragma unroll
    for (int i = 0; i < 8; i++) t += red[i];
    __syncthreads();
    return t;
}
__device__ __forceinline__ float block_max(float v, float* red) {
    int lane = threadIdx.x & 31, warp = threadIdx.x >> 5;
    #pragma unroll
    for (int o = 16; o; o >>= 1) v = fmaxf(v, __shfl_xor_sync(0xffffffffu, v, o));
    if (lane == 0) red[warp] = v;
    __syncthreads();
    float t = red[0];
    #pragma unroll
    for (int i = 1; i < 8; i++) t = fmaxf(t, red[i]);
    __syncthreads();
    return t;
}

__global__ void __launch_bounds__(256)
attn_pool_k(const float* __restrict__ H, const float* __restrict__ w,
            const int* __restrict__ mask, const float* __restrict__ X,
            float* __restrict__ out)
{
    __shared__ float sw[AADIM];
    __shared__ float sl[LLEN];
    __shared__ float smk[LLEN];
    __shared__ float red[8];

    const int b = blockIdx.x;
    const int tid = threadIdx.x;
    const int lane = tid & 31, warp = tid >> 5;

    for (int a = tid; a < AADIM; a += 256) sw[a] = w[a];
    for (int l = tid; l < LLEN; l += 256) smk[l] = (float)mask[b * LLEN + l];
    __syncthreads();

    for (int l = warp; l < LLEN; l += 8) {
        const float* Hr = H + ((size_t)b * LLEN + l) * AADIM;
        float s = 0.f;
        #pragma unroll
        for (int a = lane; a < AADIM; a += 32) s = fmaf(Hr[a], sw[a], s);
        #pragma unroll
        for (int o = 16; o; o >>= 1) s += __shfl_down_sync(0xffffffffu, s, o);
        if (lane == 0) sl[l] = s * smk[l];
    }
    __syncthreads();

    float m = -CUDART_INF_F;
    for (int l = tid; l < LLEN; l += 256) m = fmaxf(m, sl[l]);
    m = block_max(m, red);

    float psum = 0.f;
    for (int l = tid; l < LLEN; l += 256) {
        float e = expf(sl[l] - m);
        sl[l] = e; psum += e;
    }
    psum = block_sum(psum, red);
    float inv = 1.f / psum;

    float rsum = 0.f;
    for (int l = tid; l < LLEN; l += 256) {
        float r = sl[l] * inv * smk[l];
        sl[l] = r; rsum += r;
    }
    rsum = block_sum(rsum, red);
    float sc = 1.f / (rsum + 1e-13f);
    for (int l = tid; l < LLEN; l += 256) sl[l] *= sc;
    __syncthreads();

    for (int d = tid; d < DDIM; d += 256) {
        const float* Xb = X + (size_t)b * LLEN * DDIM + d;
        float acc = 0.f;
        #pragma unroll 4
        for (int l = 0; l < LLEN; l++) acc = fmaf(sl[l], Xb[(size_t)l * DDIM], acc);
        out[(size_t)b * DDIM + d] = acc;
    }
}

// ---------------- launch --------------------------------------------------------
extern "C" void kernel_launch(void* const* d_in, const int* in_sizes, int n_in,
                              void* d_out, int out_size)
{
    const float* S1    = (const float*)d_in[0];
    const float* S2    = (const float*)d_in[1];
    const int*   mask1 = (const int*)  d_in[2];
    const int*   mask2 = (const int*)  d_in[3];
    const float* W     = (const float*)d_in[4];
    const float* Wv    = (const float*)d_in[5];
    const float* Wq    = (const float*)d_in[6];
    const float* w_hv  = (const float*)d_in[7];
    const float* w_hq  = (const float*)d_in[8];
    float* out = (float*)d_out;

    __nv_bfloat16 *S1h,*S1l,*S2h,*S2l,*Wth,*Wtl,*Wvth,*Wvtl,*Wqth,*Wqtl;
    __nv_bfloat16 *Th,*Tl,*Ch,*Cl,*CTh,*CTl,*Pth,*Ptl,*Qth,*Qtl;
    float *P,*Q,*Hv,*Hq;
    cudaGetSymbolAddress((void**)&S1h, g_S1h);  cudaGetSymbolAddress((void**)&S1l, g_S1l);
    cudaGetSymbolAddress((void**)&S2h, g_S2h);  cudaGetSymbolAddress((void**)&S2l, g_S2l);
    cudaGetSymbolAddress((void**)&Wth, g_Wth);  cudaGetSymbolAddress((void**)&Wtl, g_Wtl);
    cudaGetSymbolAddress((void**)&Wvth,g_Wvth); cudaGetSymbolAddress((void**)&Wvtl,g_Wvtl);
    cudaGetSymbolAddress((void**)&Wqth,g_Wqth); cudaGetSymbolAddress((void**)&Wqtl,g_Wqtl);
    cudaGetSymbolAddress((void**)&Th,  g_Th);   cudaGetSymbolAddress((void**)&Tl,  g_Tl);
    cudaGetSymbolAddress((void**)&Ch,  g_Ch);   cudaGetSymbolAddress((void**)&Cl,  g_Cl);
    cudaGetSymbolAddress((void**)&CTh, g_CTh);  cudaGetSymbolAddress((void**)&CTl, g_CTl);
    cudaGetSymbolAddress((void**)&Pth, g_Pth);  cudaGetSymbolAddress((void**)&Ptl, g_Ptl);
    cudaGetSymbolAddress((void**)&Qth, g_Qth);  cudaGetSymbolAddress((void**)&Qtl, g_Qtl);
    cudaGetSymbolAddress((void**)&P,   g_P);    cudaGetSymbolAddress((void**)&Q,   g_Q);
    cudaGetSymbolAddress((void**)&Hv,  g_Hv);   cudaGetSymbolAddress((void**)&Hq,  g_Hq);

    cudaFuncSetAttribute(gemm_mma<0>, cudaFuncAttributeMaxDynamicSharedMemorySize, SM_BYTES);
    cudaFuncSetAttribute(gemm_mma<1>, cudaFuncAttributeMaxDynamicSharedMemorySize, SM_BYTES);
    cudaFuncSetAttribute(gemm_mma<2>, cudaFuncAttributeMaxDynamicSharedMemorySize, SM_BYTES);
    cudaFuncSetAttribute(gemm_mma<3>, cudaFuncAttributeMaxDynamicSharedMemorySize, SM_BYTES);

    const dim3 blk(256);
    const size_t sLL = (size_t)LLEN * LLEN;     // 262144
    const size_t sLA = (size_t)LLEN * AADIM;    // 131072

    // prep: split activations; transpose+split weights
    split_k<<<(BL * DDIM / 4 + 255) / 256, blk>>>((const float4*)S1, (uint2*)S1h, (uint2*)S1l, BL * DDIM / 4);
    split_k<<<(BL * DDIM / 4 + 255) / 256, blk>>>((const float4*)S2, (uint2*)S2h, (uint2*)S2l, BL * DDIM / 4);
    tsplit_k<<<dim3(DDIM / 32, DDIM / 32), blk>>>(W,  DDIM, DDIM,  Wth,  Wtl);
    tsplit_k<<<dim3(AADIM / 32, DDIM / 32), blk>>>(Wv, DDIM, AADIM, Wvth, Wvtl);
    tsplit_k<<<dim3(AADIM / 32, DDIM / 32), blk>>>(Wq, DDIM, AADIM, Wqth, Wqtl);

    // G1: T[l][d] = S1 @ W.  i=l, j=d. A=S1(h/l), B=Wt(h/l). EPI0 -> Th/Tl [l][d].
    gemm_mma<0><<<dim3(BL/128, DDIM/128, 1), blk, SM_BYTES>>>(
        S1h, S1l, 0, DDIM,  Wth, Wtl, 0, DDIM,
        nullptr, 0, 0,  nullptr, 0, 0,
        Th, Tl, 0, DDIM,  nullptr, nullptr, 0, 0);

    // G2: i=a, j=l. A=Wvt, B=S1. EPI1 -> Pt bf16 [a][BL] + P fp32 [l][a].
    gemm_mma<1><<<dim3(AADIM/128, BL/128, 1), blk, SM_BYTES>>>(
        Wvth, Wvtl, 0, DDIM,  S1h, S1l, 0, DDIM,
        nullptr, 0, 0,  P, 0, AADIM,
        Pth, Ptl, 0, BL,  nullptr, nullptr, 0, 0);

    // G3: same with Wqt, S2 -> Qt, Q.
    gemm_mma<1><<<dim3(AADIM/128, BL/128, 1), blk, SM_BYTES>>>(
        Wqth, Wqtl, 0, DDIM,  S2h, S2l, 0, DDIM,
        nullptr, 0, 0,  Q, 0, AADIM,
        Qth, Qtl, 0, BL,  nullptr, nullptr, 0, 0);

    // G4: C = tanh(T @ S2^T). i=l1, j=l2, batched. EPI2 -> C [l1][l2] + CT [l2][l1].
    gemm_mma<2><<<dim3(LLEN/128, LLEN/128, BBATCH), blk, SM_BYTES>>>(
        Th, Tl, (size_t)LLEN * DDIM, DDIM,  S2h, S2l, (size_t)LLEN * DDIM, DDIM,
        nullptr, 0, 0,  nullptr, 0, 0,
        Ch, Cl, sLL, LLEN,  CTh, CTl, sLL, LLEN);

    // G5: Hv = tanh(P + C @ Q). i=l1, j=a. A=C, B=Qt(rows a, batch offset b*512).
    gemm_mma<3><<<dim3(LLEN/128, AADIM/128, BBATCH), blk, SM_BYTES>>>(
        Ch, Cl, sLL, LLEN,  Qth, Qtl, (size_t)LLEN, BL,
        P, sLA, AADIM,  Hv, sLA, AADIM,
        nullptr, nullptr, 0, 0,  nullptr, nullptr, 0, 0);

    // G6: Hq = tanh(Q + C^T @ P). i=l2, j=a. A=CT, B=Pt.
    gemm_mma<3><<<dim3(LLEN/128, AADIM/128, BBATCH), blk, SM_BYTES>>>(
        CTh, CTl, sLL, LLEN,  Pth, Ptl, (size_t)LLEN, BL,
        Q, sLA, AADIM,  Hq, sLA, AADIM,
        nullptr, nullptr, 0, 0,  nullptr, nullptr, 0, 0);

    attn_pool_k<<<BBATCH, blk>>>(Hv, w_hv, mask1, S1, out);
    attn_pool_k<<<BBATCH, blk>>>(Hq, w_hq, mask2, S2, out + (size_t)BBATCH * DDIM);
}

// round 5
// speedup vs baseline: 1.7506x; 1.4419x over previous
#include <cuda_runtime.h>
#include <cuda_bf16.h>
#include <math_constants.h>
#include <cstdint>

#define BBATCH 64
#define LLEN   512
#define DDIM   512
#define AADIM  256
#define BL     (BBATCH * LLEN)   // 32768

// ---------------- scratch (__device__ globals) -------------------------------
__device__ __align__(256) __nv_bfloat16 g_S1h[(size_t)BL * DDIM];
__device__ __align__(256) __nv_bfloat16 g_S1l[(size_t)BL * DDIM];
__device__ __align__(256) __nv_bfloat16 g_S2h[(size_t)BL * DDIM];
__device__ __align__(256) __nv_bfloat16 g_S2l[(size_t)BL * DDIM];
__device__ __align__(256) __nv_bfloat16 g_Wth[(size_t)DDIM * DDIM];
__device__ __align__(256) __nv_bfloat16 g_Wtl[(size_t)DDIM * DDIM];
__device__ __align__(256) __nv_bfloat16 g_Wvth[(size_t)AADIM * DDIM];
__device__ __align__(256) __nv_bfloat16 g_Wvtl[(size_t)AADIM * DDIM];
__device__ __align__(256) __nv_bfloat16 g_Wqth[(size_t)AADIM * DDIM];
__device__ __align__(256) __nv_bfloat16 g_Wqtl[(size_t)AADIM * DDIM];
__device__ __align__(256) __nv_bfloat16 g_Th [(size_t)BL * DDIM];
__device__ __align__(256) __nv_bfloat16 g_Tl [(size_t)BL * DDIM];
__device__ __align__(256) __nv_bfloat16 g_Ch [(size_t)BBATCH * LLEN * LLEN];
__device__ __align__(256) __nv_bfloat16 g_Cl [(size_t)BBATCH * LLEN * LLEN];
__device__ __align__(256) __nv_bfloat16 g_CTh[(size_t)BBATCH * LLEN * LLEN];
__device__ __align__(256) __nv_bfloat16 g_CTl[(size_t)BBATCH * LLEN * LLEN];
__device__ __align__(256) __nv_bfloat16 g_Pth[(size_t)AADIM * BL];
__device__ __align__(256) __nv_bfloat16 g_Ptl[(size_t)AADIM * BL];
__device__ __align__(256) __nv_bfloat16 g_Qth[(size_t)AADIM * BL];
__device__ __align__(256) __nv_bfloat16 g_Qtl[(size_t)AADIM * BL];
__device__ __align__(256) float g_P [(size_t)BL * AADIM];
__device__ __align__(256) float g_Q [(size_t)BL * AADIM];
__device__ __align__(256) float g_Hv[(size_t)BL * AADIM];
__device__ __align__(256) float g_Hq[(size_t)BL * AADIM];

// ---------------- helpers -----------------------------------------------------
__device__ __forceinline__ uint32_t smem_u32(const void* p) {
    uint32_t a;
    asm("{ .reg .u64 t; cvta.to.shared.u64 t, %1; cvt.u32.u64 %0, t; }"
        : "=r"(a) : "l"(p));
    return a;
}
__device__ __forceinline__ uint32_t pk(__nv_bfloat16 a, __nv_bfloat16 b) {
    __nv_bfloat162 t = __halves2bfloat162(a, b);
    return *reinterpret_cast<uint32_t*>(&t);
}
__device__ __forceinline__ void split_f(float x, __nv_bfloat16& h, __nv_bfloat16& l) {
    h = __float2bfloat16(x);
    l = __float2bfloat16(x - __bfloat162float(h));
}

#define CP16(SM, G) \
    asm volatile("cp.async.cg.shared.global [%0], [%1], 16;" :: "r"(SM), "l"(G))
#define CP_COMMIT() asm volatile("cp.async.commit_group;")
#define CP_WAIT1()  asm volatile("cp.async.wait_group 1;")

#define LDSM4(R0,R1,R2,R3,ADDR) \
    asm volatile("ldmatrix.sync.aligned.m8n8.x4.shared.b16 {%0,%1,%2,%3}, [%4];" \
        : "=r"(R0),"=r"(R1),"=r"(R2),"=r"(R3) : "r"(ADDR))

__device__ __forceinline__ void mma_bf16(float* d, const uint32_t* a, const uint32_t* b) {
    asm volatile(
        "mma.sync.aligned.m16n8k16.row.col.f32.bf16.bf16.f32 "
        "{%0,%1,%2,%3}, {%4,%5,%6,%7}, {%8,%9}, {%0,%1,%2,%3};"
        : "+f"(d[0]), "+f"(d[1]), "+f"(d[2]), "+f"(d[3])
        : "r"(a[0]), "r"(a[1]), "r"(a[2]), "r"(a[3]), "r"(b[0]), "r"(b[1]));
}

// stage layout: AH 0 | AL 16K | BH 32K | BL 48K ; THREE stages of 64KB
#define STG 65536
#define SM_BYTES (3 * STG)

// one bf16 array tile: 128 rows x 64 k-elems (128B/row), SW128 xor swizzle
__device__ __forceinline__ void stage_arr(uint32_t sdst, const __nv_bfloat16* src,
                                          int rowbase, int ld, int kc, int tid)
{
    #pragma unroll
    for (int q = 0; q < 4; q++) {
        int idx = tid + q * 256;
        int r = idx >> 3, c = idx & 7;
        uint32_t sa = sdst + r * 128 + ((c ^ (r & 7)) << 4);
        const __nv_bfloat16* g = src + (size_t)(rowbase + r) * ld + kc * 64 + c * 8;
        CP16(sa, g);
    }
}

// ---------------- main MMA GEMM ------------------------------------------------
// out[i][j] = sum_k A[i][k]*B[j][k]  (A,B: bf16 hi/lo, K-major, K=512)
// EPI 0: store bf16 hi/lo natural [i][j]                          (T)
// EPI 1: EPI0 + bounce-transposed fp32 [j][i]                     (Pt/P, Qt/Q)
// EPI 2: tanh; bf16 hi/lo natural [i][j] + bounce bf16 [j][i]     (C, CT)
// EPI 3: tanh(acc + bias[i][j]); fp32 natural [i][j]              (Hv, Hq)
template<int EPI>
__global__ void __launch_bounds__(256, 1)
gemm_mma(const __nv_bfloat16* __restrict__ Ah2, const __nv_bfloat16* __restrict__ Al2,
         size_t sA, int ldA,
         const __nv_bfloat16* __restrict__ Bh2, const __nv_bfloat16* __restrict__ Bl2,
         size_t sB, int ldB,
         const float* __restrict__ bias, size_t sBias, int ldBias,
         float* __restrict__ outF, size_t sF, int ldF,
         __nv_bfloat16* __restrict__ oh, __nv_bfloat16* __restrict__ ol,
         size_t sO, int ldO,
         __nv_bfloat16* __restrict__ th, __nv_bfloat16* __restrict__ tl,
         size_t sT, int ldT)
{
    extern __shared__ char smem[];
    const int tid  = threadIdx.x;
    const int lane = tid & 31, warp = tid >> 5;
    const int wm = warp >> 2, wn = warp & 3;   // 2 x 4 warp grid
    const int z  = blockIdx.z;
    const int bi = blockIdx.x * 128, bj = blockIdx.y * 128;

    Ah2 += (size_t)z * sA;  Al2 += (size_t)z * sA;
    Bh2 += (size_t)z * sB;  Bl2 += (size_t)z * sB;
    if (EPI == 3) bias += (size_t)z * sBias;
    if (outF) outF += (size_t)z * sF;
    if (oh)   { oh += (size_t)z * sO; ol += (size_t)z * sO; }
    if (th)   { th += (size_t)z * sT; tl += (size_t)z * sT; }

    const uint32_t su = smem_u32(smem);

    float acc[4][4][4];
    #pragma unroll
    for (int a = 0; a < 4; a++)
        #pragma unroll
        for (int b = 0; b < 4; b++)
            #pragma unroll
            for (int c = 0; c < 4; c++) acc[a][b][c] = 0.f;

    const int arow_lo   = lane & 15;
    const int achunk_ad = lane >> 4;
    const int gB        = lane >> 3;
    const int brow_lo   = ((gB >> 1) << 3) + (lane & 7);
    const int bchunk_ad = gB & 1;

    uint32_t ah[2][4][4], al[2][4][4], bh[2][4][2], bl[2][4][2];

    #define LOAD_FRAGS(BUF, KB, BASE)                                            \
    do {                                                                          \
        const uint32_t aB_  = (BASE);                                             \
        const uint32_t alB_ = (BASE) + 16384;                                     \
        const uint32_t bB_  = (BASE) + 32768;                                     \
        const uint32_t blB_ = (BASE) + 49152;                                     \
        _Pragma("unroll")                                                         \
        for (int mi = 0; mi < 4; mi++) {                                          \
            int row = wm * 64 + mi * 16 + arow_lo;                                \
            int ch  = ((KB) * 2 + achunk_ad) ^ (row & 7);                         \
            uint32_t off = row * 128 + (ch << 4);                                 \
            LDSM4(ah[BUF][mi][0], ah[BUF][mi][1], ah[BUF][mi][2], ah[BUF][mi][3], aB_  + off); \
            LDSM4(al[BUF][mi][0], al[BUF][mi][1], al[BUF][mi][2], al[BUF][mi][3], alB_ + off); \
        }                                                                         \
        _Pragma("unroll")                                                         \
        for (int ng = 0; ng < 2; ng++) {                                          \
            int row = wn * 32 + ng * 16 + brow_lo;                                \
            int ch  = ((KB) * 2 + bchunk_ad) ^ (row & 7);                         \
            uint32_t off = row * 128 + (ch << 4);                                 \
            uint32_t t0, t1, t2, t3;                                              \
            LDSM4(t0, t1, t2, t3, bB_ + off);                                     \
            bh[BUF][ng*2][0] = t0; bh[BUF][ng*2][1] = t1;                         \
            bh[BUF][ng*2+1][0] = t2; bh[BUF][ng*2+1][1] = t3;                     \
            LDSM4(t0, t1, t2, t3, blB_ + off);                                    \
            bl[BUF][ng*2][0] = t0; bl[BUF][ng*2][1] = t1;                         \
            bl[BUF][ng*2+1][0] = t2; bl[BUF][ng*2+1][1] = t3;                     \
        }                                                                         \
    } while (0)

    // prologue: stage chunks 0 and 1
    {
        stage_arr(su,          Ah2, bi, ldA, 0, tid);
        stage_arr(su + 16384,  Al2, bi, ldA, 0, tid);
        stage_arr(su + 32768,  Bh2, bj, ldB, 0, tid);
        stage_arr(su + 49152,  Bl2, bj, ldB, 0, tid);
        CP_COMMIT();
        stage_arr(su + STG,         Ah2, bi, ldA, 1, tid);
        stage_arr(su + STG + 16384, Al2, bi, ldA, 1, tid);
        stage_arr(su + STG + 32768, Bh2, bj, ldB, 1, tid);
        stage_arr(su + STG + 49152, Bl2, bj, ldB, 1, tid);
        CP_COMMIT();
    }

    #pragma unroll 1
    for (int c = 0; c < 8; c++) {
        CP_WAIT1();          // own copies of chunk c retired (pending: chunk c+1)
        __syncthreads();     // everyone's chunk c visible; chunk c-1 readers done

        const uint32_t base = su + (c % 3) * STG;
        LOAD_FRAGS(0, 0, base);
        #pragma unroll
        for (int kb = 0; kb < 4; kb++) {
            const int cb = kb & 1;
            if (kb < 3) {
                LOAD_FRAGS(cb ^ 1, kb + 1, base);
            }
            #pragma unroll
            for (int mi = 0; mi < 4; mi++)
                #pragma unroll
                for (int ni = 0; ni < 4; ni++) {
                    mma_bf16(acc[mi][ni], ah[cb][mi], bh[cb][ni]);
                    mma_bf16(acc[mi][ni], ah[cb][mi], bl[cb][ni]);
                    mma_bf16(acc[mi][ni], al[cb][mi], bh[cb][ni]);
                }
        }

        if (c + 2 < 8) {     // stage chunk c+2 into buffer (c+2)%3 = (c-1)%3
            uint32_t sb = su + ((c + 2) % 3) * STG;
            stage_arr(sb,         Ah2, bi, ldA, c + 2, tid);
            stage_arr(sb + 16384, Al2, bi, ldA, c + 2, tid);
            stage_arr(sb + 32768, Bh2, bj, ldB, c + 2, tid);
            stage_arr(sb + 49152, Bl2, bj, ldB, c + 2, tid);
        }
        CP_COMMIT();         // unconditional: keeps wait_group(1) retiring the right chunk
    }
    #undef LOAD_FRAGS

    // ---------------- epilogue ----------------
    const int trow = lane >> 2;
    const int tcol = (lane & 3) * 2;

    if (EPI == 2) {
        #pragma unroll
        for (int mi = 0; mi < 4; mi++)
            #pragma unroll
            for (int ni = 0; ni < 4; ni++)
                #pragma unroll
                for (int q = 0; q < 4; q++)
                    acc[mi][ni][q] = tanhf(acc[mi][ni][q]);
    }

    if (EPI == 0 || EPI == 1 || EPI == 2) {   // natural bf16 hi/lo stores [i][j]
        #pragma unroll
        for (int mi = 0; mi < 4; mi++)
            #pragma unroll
            for (int ni = 0; ni < 4; ni++) {
                int j = bj + wn * 32 + ni * 8 + tcol;
                #pragma unroll
                for (int hf = 0; hf < 2; hf++) {
                    int i = bi + wm * 64 + mi * 16 + trow + hf * 8;
                    float v0 = acc[mi][ni][hf * 2 + 0];
                    float v1 = acc[mi][ni][hf * 2 + 1];
                    __nv_bfloat16 h0, l0, h1, l1;
                    split_f(v0, h0, l0); split_f(v1, h1, l1);
                    *(uint32_t*)&oh[(size_t)i * ldO + j] = pk(h0, h1);
                    *(uint32_t*)&ol[(size_t)i * ldO + j] = pk(l0, l1);
                }
            }
    }

    if (EPI == 1 || EPI == 2) {   // bounce transpose via smem (pitch 129 f32)
        float* smf = (float*)smem;
        __syncthreads();          // stage ring no longer needed
        #pragma unroll
        for (int mi = 0; mi < 4; mi++)
            #pragma unroll
            for (int ni = 0; ni < 4; ni++) {
                int jl = wn * 32 + ni * 8 + tcol;
                #pragma unroll
                for (int hf = 0; hf < 2; hf++) {
                    int il = wm * 64 + mi * 16 + trow + hf * 8;
                    smf[il * 129 + jl]     = acc[mi][ni][hf * 2 + 0];
                    smf[il * 129 + jl + 1] = acc[mi][ni][hf * 2 + 1];
                }
            }
        __syncthreads();
        int r2 = tid >> 1, hf2 = tid & 1;
        if (EPI == 1) {   // fp32 transposed [j][i]
            #pragma unroll 8
            for (int cc = 0; cc < 64; cc++) {
                int col = hf2 * 64 + cc;
                outF[(size_t)(bj + r2) * ldF + bi + col] = smf[col * 129 + r2];
            }
        } else {          // bf16 hi/lo transposed [j][i]
            #pragma unroll 4
            for (int cc = 0; cc < 64; cc += 2) {
                int col = hf2 * 64 + cc;
                float v0 = smf[col * 129 + r2];
                float v1 = smf[(col + 1) * 129 + r2];
                __nv_bfloat16 h0, l0, h1, l1;
                split_f(v0, h0, l0); split_f(v1, h1, l1);
                *(uint32_t*)&th[(size_t)(bj + r2) * ldT + bi + col] = pk(h0, h1);
                *(uint32_t*)&tl[(size_t)(bj + r2) * ldT + bi + col] = pk(l0, l1);
            }
        }
    }

    if (EPI == 3) {
        #pragma unroll
        for (int mi = 0; mi < 4; mi++)
            #pragma unroll
            for (int ni = 0; ni < 4; ni++) {
                int j = bj + wn * 32 + ni * 8 + tcol;
                #pragma unroll
                for (int hf = 0; hf < 2; hf++) {
                    int i = bi + wm * 64 + mi * 16 + trow + hf * 8;
                    float2 bv = *(const float2*)&bias[(size_t)i * ldBias + j];
                    float2 o;
                    o.x = tanhf(acc[mi][ni][hf * 2 + 0] + bv.x);
                    o.y = tanhf(acc[mi][ni][hf * 2 + 1] + bv.y);
                    *(float2*)&outF[(size_t)i * ldF + j] = o;
                }
            }
    }
}

// ---------------- prep kernels -------------------------------------------------
__global__ void __launch_bounds__(256)
split_k(const float4* __restrict__ in, uint2* __restrict__ hi, uint2* __restrict__ lo, int n4)
{
    int i = blockIdx.x * 256 + threadIdx.x;
    if (i >= n4) return;
    float4 v = in[i];
    __nv_bfloat16 h0,h1,h2,h3,l0,l1,l2,l3;
    split_f(v.x,h0,l0); split_f(v.y,h1,l1); split_f(v.z,h2,l2); split_f(v.w,h3,l3);
    hi[i] = make_uint2(pk(h0,h1), pk(h2,h3));
    lo[i] = make_uint2(pk(l0,l1), pk(l2,l3));
}

__global__ void __launch_bounds__(256)
tsplit_k(const float* __restrict__ in, int R, int C,
         __nv_bfloat16* __restrict__ oh, __nv_bfloat16* __restrict__ ol)
{
    __shared__ float t[32][33];
    int bx = blockIdx.x * 32, by = blockIdx.y * 32;
    int tx = threadIdx.x & 31, ty = threadIdx.x >> 5;
    #pragma unroll
    for (int i = 0; i < 32; i += 8)
        t[ty + i][tx] = in[(size_t)(by + ty + i) * C + bx + tx];
    __syncthreads();
    #pragma unroll
    for (int i = 0; i < 32; i += 8) {
        float v = t[tx][ty + i];
        __nv_bfloat16 h, l; split_f(v, h, l);
        oh[(size_t)(bx + ty + i) * R + by + tx] = h;
        ol[(size_t)(bx + ty + i) * R + by + tx] = l;
    }
}

// ---------------- masked softmax + pooling --------------------------------------
__device__ __forceinline__ float block_sum(float v, float* red) {
    int lane = threadIdx.x & 31, warp = threadIdx.x >> 5;
    #pragma unroll
    for (int o = 16; o; o >>= 1) v += __shfl_xor_sync(0xffffffffu, v, o);
    if (lane == 0) red[warp] = v;
    __syncthreads();
    float t = 0.f;
    #pragma unroll
    for (int i = 0; i < 8; i++) t += red[i];
    __syncthreads();
    return t;
}
__device__ __forceinline__ float block_max(float v, float* red) {
    int lane = threadIdx.x & 31, warp = threadIdx.x >> 5;
    #pragma unroll
    for (int o = 16; o; o >>= 1) v = fmaxf(v, __shfl_xor_sync(0xffffffffu, v, o));
    if (lane == 0) red[warp] = v;
    __syncthreads();
    float t = red[0];
    #pragma unroll
    for (int i = 1; i < 8; i++) t = fmaxf(t, red[i]);
    __syncthreads();
    return t;
}

__global__ void __launch_bounds__(256)
attn_pool_k(const float* __restrict__ H, const float* __restrict__ w,
            const int* __restrict__ mask, const float* __restrict__ X,
            float* __restrict__ out)
{
    __shared__ float sw[AADIM];
    __shared__ float sl[LLEN];
    __shared__ float smk[LLEN];
    __shared__ float red[8];

    const int b = blockIdx.x;
    const int tid = threadIdx.x;
    const int lane = tid & 31, warp = tid >> 5;

    for (int a = tid; a < AADIM; a += 256) sw[a] = w[a];
    for (int l = tid; l < LLEN; l += 256) smk[l] = (float)mask[b * LLEN + l];
    __syncthreads();

    for (int l = warp; l < LLEN; l += 8) {
        const float* Hr = H + ((size_t)b * LLEN + l) * AADIM;
        float s = 0.f;
        #pragma unroll
        for (int a = lane; a < AADIM; a += 32) s = fmaf(Hr[a], sw[a], s);
        #pragma unroll
        for (int o = 16; o; o >>= 1) s += __shfl_down_sync(0xffffffffu, s, o);
        if (lane == 0) sl[l] = s * smk[l];
    }
    __syncthreads();

    float m = -CUDART_INF_F;
    for (int l = tid; l < LLEN; l += 256) m = fmaxf(m, sl[l]);
    m = block_max(m, red);

    float psum = 0.f;
    for (int l = tid; l < LLEN; l += 256) {
        float e = expf(sl[l] - m);
        sl[l] = e; psum += e;
    }
    psum = block_sum(psum, red);
    float inv = 1.f / psum;

    float rsum = 0.f;
    for (int l = tid; l < LLEN; l += 256) {
        float r = sl[l] * inv * smk[l];
        sl[l] = r; rsum += r;
    }
    rsum = block_sum(rsum, red);
    float sc = 1.f / (rsum + 1e-13f);
    for (int l = tid; l < LLEN; l += 256) sl[l] *= sc;
    __syncthreads();

    for (int d = tid; d < DDIM; d += 256) {
        const float* Xb = X + (size_t)b * LLEN * DDIM + d;
        float acc = 0.f;
        #pragma unroll 4
        for (int l = 0; l < LLEN; l++) acc = fmaf(sl[l], Xb[(size_t)l * DDIM], acc);
        out[(size_t)b * DDIM + d] = acc;
    }
}

// ---------------- launch ---------------------------------------------------------
extern "C" void kernel_launch(void* const* d_in, const int* in_sizes, int n_in,
                              void* d_out, int out_size)
{
    const float* S1    = (const float*)d_in[0];
    const float* S2    = (const float*)d_in[1];
    const int*   mask1 = (const int*)  d_in[2];
    const int*   mask2 = (const int*)  d_in[3];
    const float* W     = (const float*)d_in[4];
    const float* Wv    = (const float*)d_in[5];
    const float* Wq    = (const float*)d_in[6];
    const float* w_hv  = (const float*)d_in[7];
    const float* w_hq  = (const float*)d_in[8];
    float* out = (float*)d_out;

    __nv_bfloat16 *S1h,*S1l,*S2h,*S2l,*Wth,*Wtl,*Wvth,*Wvtl,*Wqth,*Wqtl;
    __nv_bfloat16 *Th,*Tl,*Ch,*Cl,*CTh,*CTl,*Pth,*Ptl,*Qth,*Qtl;
    float *P,*Q,*Hv,*Hq;
    cudaGetSymbolAddress((void**)&S1h, g_S1h);  cudaGetSymbolAddress((void**)&S1l, g_S1l);
    cudaGetSymbolAddress((void**)&S2h, g_S2h);  cudaGetSymbolAddress((void**)&S2l, g_S2l);
    cudaGetSymbolAddress((void**)&Wth, g_Wth);  cudaGetSymbolAddress((void**)&Wtl, g_Wtl);
    cudaGetSymbolAddress((void**)&Wvth,g_Wvth); cudaGetSymbolAddress((void**)&Wvtl,g_Wvtl);
    cudaGetSymbolAddress((void**)&Wqth,g_Wqth); cudaGetSymbolAddress((void**)&Wqtl,g_Wqtl);
    cudaGetSymbolAddress((void**)&Th,  g_Th);   cudaGetSymbolAddress((void**)&Tl,  g_Tl);
    cudaGetSymbolAddress((void**)&Ch,  g_Ch);   cudaGetSymbolAddress((void**)&Cl,  g_Cl);
    cudaGetSymbolAddress((void**)&CTh, g_CTh);  cudaGetSymbolAddress((void**)&CTl, g_CTl);
    cudaGetSymbolAddress((void**)&Pth, g_Pth);  cudaGetSymbolAddress((void**)&Ptl, g_Ptl);
    cudaGetSymbolAddress((void**)&Qth, g_Qth);  cudaGetSymbolAddress((void**)&Qtl, g_Qtl);
    cudaGetSymbolAddress((void**)&P,   g_P);    cudaGetSymbolAddress((void**)&Q,   g_Q);
    cudaGetSymbolAddress((void**)&Hv,  g_Hv);   cudaGetSymbolAddress((void**)&Hq,  g_Hq);

    cudaFuncSetAttribute(gemm_mma<0>, cudaFuncAttributeMaxDynamicSharedMemorySize, SM_BYTES);
    cudaFuncSetAttribute(gemm_mma<1>, cudaFuncAttributeMaxDynamicSharedMemorySize, SM_BYTES);
    cudaFuncSetAttribute(gemm_mma<2>, cudaFuncAttributeMaxDynamicSharedMemorySize, SM_BYTES);
    cudaFuncSetAttribute(gemm_mma<3>, cudaFuncAttributeMaxDynamicSharedMemorySize, SM_BYTES);

    const dim3 blk(256);
    const size_t sLL = (size_t)LLEN * LLEN;
    const size_t sLA = (size_t)LLEN * AADIM;

    split_k<<<(BL * DDIM / 4 + 255) / 256, blk>>>((const float4*)S1, (uint2*)S1h, (uint2*)S1l, BL * DDIM / 4);
    split_k<<<(BL * DDIM / 4 + 255) / 256, blk>>>((const float4*)S2, (uint2*)S2h, (uint2*)S2l, BL * DDIM / 4);
    tsplit_k<<<dim3(DDIM / 32, DDIM / 32), blk>>>(W,  DDIM, DDIM,  Wth,  Wtl);
    tsplit_k<<<dim3(AADIM / 32, DDIM / 32), blk>>>(Wv, DDIM, AADIM, Wvth, Wvtl);
    tsplit_k<<<dim3(AADIM / 32, DDIM / 32), blk>>>(Wq, DDIM, AADIM, Wqth, Wqtl);

    // G1: T = S1 @ W.  i=l, j=d. EPI0 -> Th/Tl [l][d].
    gemm_mma<0><<<dim3(BL/128, DDIM/128, 1), blk, SM_BYTES>>>(
        S1h, S1l, 0, DDIM,  Wth, Wtl, 0, DDIM,
        nullptr, 0, 0,  nullptr, 0, 0,
        Th, Tl, 0, DDIM,  nullptr, nullptr, 0, 0);

    // G2: i=a, j=l. EPI1 -> Pt bf16 natural [a][BL] + P fp32 transposed [l][a].
    gemm_mma<1><<<dim3(AADIM/128, BL/128, 1), blk, SM_BYTES>>>(
        Wvth, Wvtl, 0, DDIM,  S1h, S1l, 0, DDIM,
        nullptr, 0, 0,  P, 0, AADIM,
        Pth, Ptl, 0, BL,  nullptr, nullptr, 0, 0);

    // G3: -> Qt bf16 [a][BL] + Q fp32 [l][a].
    gemm_mma<1><<<dim3(AADIM/128, BL/128, 1), blk, SM_BYTES>>>(
        Wqth, Wqtl, 0, DDIM,  S2h, S2l, 0, DDIM,
        nullptr, 0, 0,  Q, 0, AADIM,
        Qth, Qtl, 0, BL,  nullptr, nullptr, 0, 0);

    // G4: C = tanh(T @ S2^T). EPI2 -> C [l1][l2] + CT [l2][l1].
    gemm_mma<2><<<dim3(LLEN/128, LLEN/128, BBATCH), blk, SM_BYTES>>>(
        Th, Tl, (size_t)LLEN * DDIM, DDIM,  S2h, S2l, (size_t)LLEN * DDIM, DDIM,
        nullptr, 0, 0,  nullptr, 0, 0,
        Ch, Cl, sLL, LLEN,  CTh, CTl, sLL, LLEN);

    // G5: Hv = tanh(P + C @ Q). i=l1, j=a. B = Qt rows (ld=BL, batch offset z*LLEN).
    gemm_mma<3><<<dim3(LLEN/128, AADIM/128, BBATCH), blk, SM_BYTES>>>(
        Ch, Cl, sLL, LLEN,  Qth, Qtl, (size_t)LLEN, BL,
        P, sLA, AADIM,  Hv, sLA, AADIM,
        nullptr, nullptr, 0, 0,  nullptr, nullptr, 0, 0);

    // G6: Hq = tanh(Q + C^T @ P). i=l2, j=a. B = Pt.
    gemm_mma<3><<<dim3(LLEN/128, AADIM/128, BBATCH), blk, SM_BYTES>>>(
        CTh, CTl, sLL, LLEN,  Pth, Ptl, (size_t)LLEN, BL,
        Q, sLA, AADIM,  Hq, sLA, AADIM,
        nullptr, nullptr, 0, 0,  nullptr, nullptr, 0, 0);

    attn_pool_k<<<BBATCH, blk>>>(Hv, w_hv, mask1, S1, out);
    attn_pool_k<<<BBATCH, blk>>>(Hq, w_hq, mask2, S2, out + (size_t)BBATCH * DDIM);
}

// round 6
// speedup vs baseline: 1.8888x; 1.0789x over previous
#include <cuda_runtime.h>
#include <cuda_bf16.h>
#include <math_constants.h>
#include <cstdint>

#define BBATCH 64
#define LLEN   512
#define DDIM   512
#define AADIM  256
#define BL     (BBATCH * LLEN)   // 32768

// ---------------- scratch (__device__ globals) -------------------------------
__device__ __align__(256) __nv_bfloat16 g_S1h[(size_t)BL * DDIM];
__device__ __align__(256) __nv_bfloat16 g_S1l[(size_t)BL * DDIM];
__device__ __align__(256) __nv_bfloat16 g_S2h[(size_t)BL * DDIM];
__device__ __align__(256) __nv_bfloat16 g_S2l[(size_t)BL * DDIM];
__device__ __align__(256) __nv_bfloat16 g_Wth[(size_t)DDIM * DDIM];
__device__ __align__(256) __nv_bfloat16 g_Wtl[(size_t)DDIM * DDIM];
__device__ __align__(256) __nv_bfloat16 g_Wvth[(size_t)AADIM * DDIM];
__device__ __align__(256) __nv_bfloat16 g_Wvtl[(size_t)AADIM * DDIM];
__device__ __align__(256) __nv_bfloat16 g_Wqth[(size_t)AADIM * DDIM];
__device__ __align__(256) __nv_bfloat16 g_Wqtl[(size_t)AADIM * DDIM];
__device__ __align__(256) __nv_bfloat16 g_Th [(size_t)BL * DDIM];
__device__ __align__(256) __nv_bfloat16 g_Tl [(size_t)BL * DDIM];
__device__ __align__(256) __nv_bfloat16 g_Ch [(size_t)BBATCH * LLEN * LLEN];
__device__ __align__(256) __nv_bfloat16 g_Cl [(size_t)BBATCH * LLEN * LLEN];
__device__ __align__(256) __nv_bfloat16 g_CTh[(size_t)BBATCH * LLEN * LLEN];
__device__ __align__(256) __nv_bfloat16 g_CTl[(size_t)BBATCH * LLEN * LLEN];
__device__ __align__(256) __nv_bfloat16 g_Pth[(size_t)AADIM * BL];
__device__ __align__(256) __nv_bfloat16 g_Ptl[(size_t)AADIM * BL];
__device__ __align__(256) __nv_bfloat16 g_Qth[(size_t)AADIM * BL];
__device__ __align__(256) __nv_bfloat16 g_Qtl[(size_t)AADIM * BL];
__device__ __align__(256) float g_P [(size_t)BL * AADIM];
__device__ __align__(256) float g_Q [(size_t)BL * AADIM];
__device__ __align__(256) float g_Hv[(size_t)BL * AADIM];
__device__ __align__(256) float g_Hq[(size_t)BL * AADIM];

// ---------------- helpers -----------------------------------------------------
__device__ __forceinline__ uint32_t smem_u32(const void* p) {
    uint32_t a;
    asm("{ .reg .u64 t; cvta.to.shared.u64 t, %1; cvt.u32.u64 %0, t; }"
        : "=r"(a) : "l"(p));
    return a;
}
__device__ __forceinline__ uint32_t pk(__nv_bfloat16 a, __nv_bfloat16 b) {
    __nv_bfloat162 t = __halves2bfloat162(a, b);
    return *reinterpret_cast<uint32_t*>(&t);
}
__device__ __forceinline__ void split_f(float x, __nv_bfloat16& h, __nv_bfloat16& l) {
    h = __float2bfloat16(x);
    l = __float2bfloat16(x - __bfloat162float(h));
}

#define CP16(SM, G) \
    asm volatile("cp.async.cg.shared.global [%0], [%1], 16;" :: "r"(SM), "l"(G))
#define CP_COMMIT() asm volatile("cp.async.commit_group;")
#define CP_WAIT1()  asm volatile("cp.async.wait_group 1;")

#define LDSM4(R0,R1,R2,R3,ADDR) \
    asm volatile("ldmatrix.sync.aligned.m8n8.x4.shared.b16 {%0,%1,%2,%3}, [%4];" \
        : "=r"(R0),"=r"(R1),"=r"(R2),"=r"(R3) : "r"(ADDR))

__device__ __forceinline__ void mma_bf16(float* d, const uint32_t* a, const uint32_t* b) {
    asm volatile(
        "mma.sync.aligned.m16n8k16.row.col.f32.bf16.bf16.f32 "
        "{%0,%1,%2,%3}, {%4,%5,%6,%7}, {%8,%9}, {%0,%1,%2,%3};"
        : "+f"(d[0]), "+f"(d[1]), "+f"(d[2]), "+f"(d[3])
        : "r"(a[0]), "r"(a[1]), "r"(a[2]), "r"(a[3]), "r"(b[0]), "r"(b[1]));
}

// stage layout per 98304B stage: AH 0 | AL 16K | BH 32K | BL2 64K  (B is 256 rows)
#define STG      98304
#define SM_BYTES 196608

// one bf16 array tile: ROWS x 64 K bf16 (128B/row), SW128 xor swizzle
template<int ROWS>
__device__ __forceinline__ void stage_arr(uint32_t sdst, const __nv_bfloat16* src,
                                          int rowbase, int ld, int kc, int tid)
{
    #pragma unroll
    for (int q = 0; q < ROWS / 32; q++) {
        int idx = tid + q * 256;
        int r = idx >> 3, c = idx & 7;
        uint32_t sa = sdst + r * 128 + ((c ^ (r & 7)) << 4);
        const __nv_bfloat16* g = src + (size_t)(rowbase + r) * ld + kc * 64 + c * 8;
        CP16(sa, g);
    }
}

// ---------------- main MMA GEMM ------------------------------------------------
// CTA tile 128(M) x 256(N), 8 warps 2x4, warp tile 64x64. K=512 in 8 chunks of 64.
// out[i][j] = sum_k A[i][k]*B[j][k]  (A,B: bf16 hi/lo, K-major)
// EPI 0: natural bf16 hi/lo [i][j]                                   (T)
// EPI 1: natural fp32 [i][j] + bounce-transposed bf16 hi/lo [j][i]   (P+Pt, Q+Qt)
// EPI 2: tanh; natural bf16 [i][j] + bounce bf16 [j][i]              (C, CT)
// EPI 3: tanh(acc + bias[i][j]); fp32 natural [i][j]                 (Hv, Hq)
template<int EPI>
__global__ void __launch_bounds__(256, 1)
gemm_mma(const __nv_bfloat16* __restrict__ Ah2, const __nv_bfloat16* __restrict__ Al2,
         size_t sA, int ldA,
         const __nv_bfloat16* __restrict__ Bh2, const __nv_bfloat16* __restrict__ Bl2,
         size_t sB, int ldB,
         const float* __restrict__ bias, size_t sBias, int ldBias,
         float* __restrict__ outF, size_t sF, int ldF,
         __nv_bfloat16* __restrict__ oh, __nv_bfloat16* __restrict__ ol,
         size_t sO, int ldO,
         __nv_bfloat16* __restrict__ th, __nv_bfloat16* __restrict__ tl,
         size_t sT, int ldT)
{
    extern __shared__ char smem[];
    const int tid  = threadIdx.x;
    const int lane = tid & 31, warp = tid >> 5;
    const int wm = warp >> 2, wn = warp & 3;   // 2 x 4 warp grid
    const int z  = blockIdx.z;
    const int bi = blockIdx.x * 128, bj = blockIdx.y * 256;

    Ah2 += (size_t)z * sA;  Al2 += (size_t)z * sA;
    Bh2 += (size_t)z * sB;  Bl2 += (size_t)z * sB;
    if (EPI == 3) bias += (size_t)z * sBias;
    if (outF) outF += (size_t)z * sF;
    if (oh)   { oh += (size_t)z * sO; ol += (size_t)z * sO; }
    if (th)   { th += (size_t)z * sT; tl += (size_t)z * sT; }

    const uint32_t su = smem_u32(smem);

    float acc[4][8][4];
    #pragma unroll
    for (int a = 0; a < 4; a++)
        #pragma unroll
        for (int b = 0; b < 8; b++)
            #pragma unroll
            for (int c = 0; c < 4; c++) acc[a][b][c] = 0.f;

    const int arow_lo   = lane & 15;
    const int achunk_ad = lane >> 4;
    const int gB        = lane >> 3;
    const int brow_lo   = ((gB >> 1) << 3) + (lane & 7);
    const int bchunk_ad = gB & 1;

    // prologue: stage chunks 0 and 1
    #pragma unroll
    for (int pc = 0; pc < 2; pc++) {
        uint32_t sb = su + pc * STG;
        stage_arr<128>(sb,         Ah2, bi, ldA, pc, tid);
        stage_arr<128>(sb + 16384, Al2, bi, ldA, pc, tid);
        stage_arr<256>(sb + 32768, Bh2, bj, ldB, pc, tid);
        stage_arr<256>(sb + 65536, Bl2, bj, ldB, pc, tid);
        CP_COMMIT();
    }

    #pragma unroll 1
    for (int c = 0; c < 8; c++) {
        CP_WAIT1();          // own copies of chunk c retired
        __syncthreads();     // everyone's chunk c visible

        const uint32_t base = su + (c & 1) * STG;
        const uint32_t aB  = base;
        const uint32_t alB = base + 16384;
        const uint32_t bB  = base + 32768;
        const uint32_t blB = base + 65536;

        #pragma unroll
        for (int kb = 0; kb < 4; kb++) {
            uint32_t ah[4][4], al[4][4], bh[8][2], blr[8][2];
            #pragma unroll
            for (int mi = 0; mi < 4; mi++) {
                int row = wm * 64 + mi * 16 + arow_lo;
                int ch  = (kb * 2 + achunk_ad) ^ (row & 7);
                uint32_t off = row * 128 + (ch << 4);
                LDSM4(ah[mi][0], ah[mi][1], ah[mi][2], ah[mi][3], aB  + off);
                LDSM4(al[mi][0], al[mi][1], al[mi][2], al[mi][3], alB + off);
            }
            #pragma unroll
            for (int ng = 0; ng < 4; ng++) {
                int row = wn * 64 + ng * 16 + brow_lo;
                int ch  = (kb * 2 + bchunk_ad) ^ (row & 7);
                uint32_t off = row * 128 + (ch << 4);
                uint32_t t0, t1, t2, t3;
                LDSM4(t0, t1, t2, t3, bB + off);
                bh[ng*2][0] = t0; bh[ng*2][1] = t1;
                bh[ng*2+1][0] = t2; bh[ng*2+1][1] = t3;
                LDSM4(t0, t1, t2, t3, blB + off);
                blr[ng*2][0] = t0; blr[ng*2][1] = t1;
                blr[ng*2+1][0] = t2; blr[ng*2+1][1] = t3;
            }
            #pragma unroll
            for (int mi = 0; mi < 4; mi++)
                #pragma unroll
                for (int ni = 0; ni < 8; ni++) {
                    mma_bf16(acc[mi][ni], ah[mi], bh[ni]);
                    mma_bf16(acc[mi][ni], ah[mi], blr[ni]);
                    mma_bf16(acc[mi][ni], al[mi], bh[ni]);
                }
        }

        __syncthreads();     // all readers of chunk c done; buffer reusable
        if (c + 2 < 8) {
            uint32_t sb = su + (c & 1) * STG;
            stage_arr<128>(sb,         Ah2, bi, ldA, c + 2, tid);
            stage_arr<128>(sb + 16384, Al2, bi, ldA, c + 2, tid);
            stage_arr<256>(sb + 32768, Bh2, bj, ldB, c + 2, tid);
            stage_arr<256>(sb + 65536, Bl2, bj, ldB, c + 2, tid);
        }
        CP_COMMIT();         // unconditional: uniform group arithmetic
    }

    // ---------------- epilogue ----------------
    const int trow = lane >> 2;
    const int tcol = (lane & 3) * 2;

    if (EPI == 2 || EPI == 3) {
        #pragma unroll
        for (int mi = 0; mi < 4; mi++)
            #pragma unroll
            for (int ni = 0; ni < 8; ni++) {
                int j = bj + wn * 64 + ni * 8 + tcol;
                #pragma unroll
                for (int hf = 0; hf < 2; hf++) {
                    int i = bi + wm * 64 + mi * 16 + trow + hf * 8;
                    float x0 = acc[mi][ni][hf * 2 + 0];
                    float x1 = acc[mi][ni][hf * 2 + 1];
                    if (EPI == 3) {
                        float2 bv = *(const float2*)&bias[(size_t)i * ldBias + j];
                        x0 += bv.x; x1 += bv.y;
                    }
                    acc[mi][ni][hf * 2 + 0] = tanhf(x0);
                    acc[mi][ni][hf * 2 + 1] = tanhf(x1);
                }
            }
    }

    if (EPI == 0 || EPI == 2) {   // natural bf16 hi/lo stores [i][j]
        #pragma unroll
        for (int mi = 0; mi < 4; mi++)
            #pragma unroll
            for (int ni = 0; ni < 8; ni++) {
                int j = bj + wn * 64 + ni * 8 + tcol;
                #pragma unroll
                for (int hf = 0; hf < 2; hf++) {
                    int i = bi + wm * 64 + mi * 16 + trow + hf * 8;
                    float v0 = acc[mi][ni][hf * 2 + 0];
                    float v1 = acc[mi][ni][hf * 2 + 1];
                    __nv_bfloat16 h0, l0, h1, l1;
                    split_f(v0, h0, l0); split_f(v1, h1, l1);
                    *(uint32_t*)&oh[(size_t)i * ldO + j] = pk(h0, h1);
                    *(uint32_t*)&ol[(size_t)i * ldO + j] = pk(l0, l1);
                }
            }
    }

    if (EPI == 1 || EPI == 3) {   // natural fp32 stores [i][j]
        #pragma unroll
        for (int mi = 0; mi < 4; mi++)
            #pragma unroll
            for (int ni = 0; ni < 8; ni++) {
                int j = bj + wn * 64 + ni * 8 + tcol;
                #pragma unroll
                for (int hf = 0; hf < 2; hf++) {
                    int i = bi + wm * 64 + mi * 16 + trow + hf * 8;
                    float2 o;
                    o.x = acc[mi][ni][hf * 2 + 0];
                    o.y = acc[mi][ni][hf * 2 + 1];
                    *(float2*)&outF[(size_t)i * ldF + j] = o;
                }
            }
    }

    if (EPI == 1 || EPI == 2) {   // bounce-transposed bf16 hi/lo [j][i]
        float* smf = (float*)smem;   // 128 x 256, pitch 257 f32 (131.5 KB)
        // mainloop ended with __syncthreads; stage ring is dead. Write bounce.
        #pragma unroll
        for (int mi = 0; mi < 4; mi++)
            #pragma unroll
            for (int ni = 0; ni < 8; ni++) {
                int jl = wn * 64 + ni * 8 + tcol;
                #pragma unroll
                for (int hf = 0; hf < 2; hf++) {
                    int il = wm * 64 + mi * 16 + trow + hf * 8;
                    smf[il * 257 + jl]     = acc[mi][ni][hf * 2 + 0];
                    smf[il * 257 + jl + 1] = acc[mi][ni][hf * 2 + 1];
                }
            }
        __syncthreads();
        // coalesced readout: warp handles rows jj = warp + 8*jrep; lane covers 4 i's
        const int ii0 = lane * 4;
        #pragma unroll 4
        for (int jrep = 0; jrep < 32; jrep++) {
            int jj = warp + jrep * 8;
            float v0 = smf[(ii0 + 0) * 257 + jj];
            float v1 = smf[(ii0 + 1) * 257 + jj];
            float v2 = smf[(ii0 + 2) * 257 + jj];
            float v3 = smf[(ii0 + 3) * 257 + jj];
            __nv_bfloat16 h0,l0,h1,l1,h2,l2,h3,l3;
            split_f(v0,h0,l0); split_f(v1,h1,l1); split_f(v2,h2,l2); split_f(v3,h3,l3);
            size_t base_o = (size_t)(bj + jj) * ldT + bi + ii0;
            *(uint2*)&th[base_o] = make_uint2(pk(h0,h1), pk(h2,h3));
            *(uint2*)&tl[base_o] = make_uint2(pk(l0,l1), pk(l2,l3));
        }
    }
}

// ---------------- prep kernels -------------------------------------------------
__global__ void __launch_bounds__(256)
split_k(const float4* __restrict__ in, uint2* __restrict__ hi, uint2* __restrict__ lo, int n4)
{
    int i = blockIdx.x * 256 + threadIdx.x;
    if (i >= n4) return;
    float4 v = in[i];
    __nv_bfloat16 h0,h1,h2,h3,l0,l1,l2,l3;
    split_f(v.x,h0,l0); split_f(v.y,h1,l1); split_f(v.z,h2,l2); split_f(v.w,h3,l3);
    hi[i] = make_uint2(pk(h0,h1), pk(h2,h3));
    lo[i] = make_uint2(pk(l0,l1), pk(l2,l3));
}

__global__ void __launch_bounds__(256)
tsplit_k(const float* __restrict__ in, int R, int C,
         __nv_bfloat16* __restrict__ oh, __nv_bfloat16* __restrict__ ol)
{
    __shared__ float t[32][33];
    int bx = blockIdx.x * 32, by = blockIdx.y * 32;
    int tx = threadIdx.x & 31, ty = threadIdx.x >> 5;
    #pragma unroll
    for (int i = 0; i < 32; i += 8)
        t[ty + i][tx] = in[(size_t)(by + ty + i) * C + bx + tx];
    __syncthreads();
    #pragma unroll
    for (int i = 0; i < 32; i += 8) {
        float v = t[tx][ty + i];
        __nv_bfloat16 h, l; split_f(v, h, l);
        oh[(size_t)(bx + ty + i) * R + by + tx] = h;
        ol[(size_t)(bx + ty + i) * R + by + tx] = l;
    }
}

// ---------------- masked softmax + pooling --------------------------------------
__device__ __forceinline__ float block_sum(float v, float* red) {
    int lane = threadIdx.x & 31, warp = threadIdx.x >> 5;
    #pragma unroll
    for (int o = 16; o; o >>= 1) v += __shfl_xor_sync(0xffffffffu, v, o);
    if (lane == 0) red[warp] = v;
    __syncthreads();
    float t = 0.f;
    #pragma unroll
    for (int i = 0; i < 8; i++) t += red[i];
    __syncthreads();
    return t;
}
__device__ __forceinline__ float block_max(float v, float* red) {
    int lane = threadIdx.x & 31, warp = threadIdx.x >> 5;
    #pragma unroll
    for (int o = 16; o; o >>= 1) v = fmaxf(v, __shfl_xor_sync(0xffffffffu, v, o));
    if (lane == 0) red[warp] = v;
    __syncthreads();
    float t = red[0];
    #pragma unroll
    for (int i = 1; i < 8; i++) t = fmaxf(t, red[i]);
    __syncthreads();
    return t;
}

__global__ void __launch_bounds__(256)
attn_pool_k(const float* __restrict__ H, const float* __restrict__ w,
            const int* __restrict__ mask, const float* __restrict__ X,
            float* __restrict__ out)
{
    __shared__ float sw[AADIM];
    __shared__ float sl[LLEN];
    __shared__ float smk[LLEN];
    __shared__ float red[8];

    const int b = blockIdx.x;
    const int tid = threadIdx.x;
    const int lane = tid & 31, warp = tid >> 5;

    for (int a = tid; a < AADIM; a += 256) sw[a] = w[a];
    for (int l = tid; l < LLEN; l += 256) smk[l] = (float)mask[b * LLEN + l];
    __syncthreads();

    for (int l = warp; l < LLEN; l += 8) {
        const float* Hr = H + ((size_t)b * LLEN + l) * AADIM;
        float s = 0.f;
        #pragma unroll
        for (int a = lane; a < AADIM; a += 32) s = fmaf(Hr[a], sw[a], s);
        #pragma unroll
        for (int o = 16; o; o >>= 1) s += __shfl_down_sync(0xffffffffu, s, o);
        if (lane == 0) sl[l] = s * smk[l];
    }
    __syncthreads();

    float m = -CUDART_INF_F;
    for (int l = tid; l < LLEN; l += 256) m = fmaxf(m, sl[l]);
    m = block_max(m, red);

    float psum = 0.f;
    for (int l = tid; l < LLEN; l += 256) {
        float e = expf(sl[l] - m);
        sl[l] = e; psum += e;
    }
    psum = block_sum(psum, red);
    float inv = 1.f / psum;

    float rsum = 0.f;
    for (int l = tid; l < LLEN; l += 256) {
        float r = sl[l] * inv * smk[l];
        sl[l] = r; rsum += r;
    }
    rsum = block_sum(rsum, red);
    float sc = 1.f / (rsum + 1e-13f);
    for (int l = tid; l < LLEN; l += 256) sl[l] *= sc;
    __syncthreads();

    for (int d = tid; d < DDIM; d += 256) {
        const float* Xb = X + (size_t)b * LLEN * DDIM + d;
        float acc = 0.f;
        #pragma unroll 4
        for (int l = 0; l < LLEN; l++) acc = fmaf(sl[l], Xb[(size_t)l * DDIM], acc);
        out[(size_t)b * DDIM + d] = acc;
    }
}

// ---------------- launch ---------------------------------------------------------
extern "C" void kernel_launch(void* const* d_in, const int* in_sizes, int n_in,
                              void* d_out, int out_size)
{
    const float* S1    = (const float*)d_in[0];
    const float* S2    = (const float*)d_in[1];
    const int*   mask1 = (const int*)  d_in[2];
    const int*   mask2 = (const int*)  d_in[3];
    const float* W     = (const float*)d_in[4];
    const float* Wv    = (const float*)d_in[5];
    const float* Wq    = (const float*)d_in[6];
    const float* w_hv  = (const float*)d_in[7];
    const float* w_hq  = (const float*)d_in[8];
    float* out = (float*)d_out;

    __nv_bfloat16 *S1h,*S1l,*S2h,*S2l,*Wth,*Wtl,*Wvth,*Wvtl,*Wqth,*Wqtl;
    __nv_bfloat16 *Th,*Tl,*Ch,*Cl,*CTh,*CTl,*Pth,*Ptl,*Qth,*Qtl;
    float *P,*Q,*Hv,*Hq;
    cudaGetSymbolAddress((void**)&S1h, g_S1h);  cudaGetSymbolAddress((void**)&S1l, g_S1l);
    cudaGetSymbolAddress((void**)&S2h, g_S2h);  cudaGetSymbolAddress((void**)&S2l, g_S2l);
    cudaGetSymbolAddress((void**)&Wth, g_Wth);  cudaGetSymbolAddress((void**)&Wtl, g_Wtl);
    cudaGetSymbolAddress((void**)&Wvth,g_Wvth); cudaGetSymbolAddress((void**)&Wvtl,g_Wvtl);
    cudaGetSymbolAddress((void**)&Wqth,g_Wqth); cudaGetSymbolAddress((void**)&Wqtl,g_Wqtl);
    cudaGetSymbolAddress((void**)&Th,  g_Th);   cudaGetSymbolAddress((void**)&Tl,  g_Tl);
    cudaGetSymbolAddress((void**)&Ch,  g_Ch);   cudaGetSymbolAddress((void**)&Cl,  g_Cl);
    cudaGetSymbolAddress((void**)&CTh, g_CTh);  cudaGetSymbolAddress((void**)&CTl, g_CTl);
    cudaGetSymbolAddress((void**)&Pth, g_Pth);  cudaGetSymbolAddress((void**)&Ptl, g_Ptl);
    cudaGetSymbolAddress((void**)&Qth, g_Qth);  cudaGetSymbolAddress((void**)&Qtl, g_Qtl);
    cudaGetSymbolAddress((void**)&P,   g_P);    cudaGetSymbolAddress((void**)&Q,   g_Q);
    cudaGetSymbolAddress((void**)&Hv,  g_Hv);   cudaGetSymbolAddress((void**)&Hq,  g_Hq);

    cudaFuncSetAttribute(gemm_mma<0>, cudaFuncAttributeMaxDynamicSharedMemorySize, SM_BYTES);
    cudaFuncSetAttribute(gemm_mma<1>, cudaFuncAttributeMaxDynamicSharedMemorySize, SM_BYTES);
    cudaFuncSetAttribute(gemm_mma<2>, cudaFuncAttributeMaxDynamicSharedMemorySize, SM_BYTES);
    cudaFuncSetAttribute(gemm_mma<3>, cudaFuncAttributeMaxDynamicSharedMemorySize, SM_BYTES);

    const dim3 blk(256);
    const size_t sLL = (size_t)LLEN * LLEN;
    const size_t sLA = (size_t)LLEN * AADIM;
    const size_t sLD = (size_t)LLEN * DDIM;

    split_k<<<(BL * DDIM / 4 + 255) / 256, blk>>>((const float4*)S1, (uint2*)S1h, (uint2*)S1l, BL * DDIM / 4);
    split_k<<<(BL * DDIM / 4 + 255) / 256, blk>>>((const float4*)S2, (uint2*)S2h, (uint2*)S2l, BL * DDIM / 4);
    tsplit_k<<<dim3(DDIM / 32, DDIM / 32), blk>>>(W,  DDIM, DDIM,  Wth,  Wtl);
    tsplit_k<<<dim3(AADIM / 32, DDIM / 32), blk>>>(Wv, DDIM, AADIM, Wvth, Wvtl);
    tsplit_k<<<dim3(AADIM / 32, DDIM / 32), blk>>>(Wq, DDIM, AADIM, Wqth, Wqtl);

    // G1: T = S1 @ W.  i=l (BL), j=d (512). EPI0 -> Th/Tl [l][d].
    gemm_mma<0><<<dim3(BL/128, DDIM/256, 1), blk, SM_BYTES>>>(
        S1h, S1l, 0, DDIM,  Wth, Wtl, 0, DDIM,
        nullptr, 0, 0,  nullptr, 0, 0,
        Th, Tl, 0, DDIM,  nullptr, nullptr, 0, 0);

    // G2: i=l (BL), j=a (256). EPI1 -> P fp32 [l][a] + Pt bf16 [a][BL].
    gemm_mma<1><<<dim3(BL/128, 1, 1), blk, SM_BYTES>>>(
        S1h, S1l, 0, DDIM,  Wvth, Wvtl, 0, DDIM,
        nullptr, 0, 0,  P, 0, AADIM,
        nullptr, nullptr, 0, 0,  Pth, Ptl, 0, BL);

    // G3: -> Q fp32 [l][a] + Qt bf16 [a][BL].
    gemm_mma<1><<<dim3(BL/128, 1, 1), blk, SM_BYTES>>>(
        S2h, S2l, 0, DDIM,  Wqth, Wqtl, 0, DDIM,
        nullptr, 0, 0,  Q, 0, AADIM,
        nullptr, nullptr, 0, 0,  Qth, Qtl, 0, BL);

    // G4: C = tanh(T @ S2^T). i=l1, j=l2, batched. EPI2 -> C [l1][l2] + CT [l2][l1].
    gemm_mma<2><<<dim3(LLEN/128, LLEN/256, BBATCH), blk, SM_BYTES>>>(
        Th, Tl, sLD, DDIM,  S2h, S2l, sLD, DDIM,
        nullptr, 0, 0,  nullptr, 0, 0,
        Ch, Cl, sLL, LLEN,  CTh, CTl, sLL, LLEN);

    // G5: Hv = tanh(P + C @ Q). i=l1, j=a. B = Qt (ld BL, batch offset z*LLEN).
    gemm_mma<3><<<dim3(LLEN/128, 1, BBATCH), blk, SM_BYTES>>>(
        Ch, Cl, sLL, LLEN,  Qth, Qtl, (size_t)LLEN, BL,
        P, sLA, AADIM,  Hv, sLA, AADIM,
        nullptr, nullptr, 0, 0,  nullptr, nullptr, 0, 0);

    // G6: Hq = tanh(Q + C^T @ P). i=l2, j=a. B = Pt.
    gemm_mma<3><<<dim3(LLEN/128, 1, BBATCH), blk, SM_BYTES>>>(
        CTh, CTl, sLL, LLEN,  Pth, Ptl, (size_t)LLEN, BL,
        Q, sLA, AADIM,  Hq, sLA, AADIM,
        nullptr, nullptr, 0, 0,  nullptr, nullptr, 0, 0);

    attn_pool_k<<<BBATCH, blk>>>(Hv, w_hv, mask1, S1, out);
    attn_pool_k<<<BBATCH, blk>>>(Hq, w_hq, mask2, S2, out + (size_t)BBATCH * DDIM);
}

// round 7
// speedup vs baseline: 2.0454x; 1.0829x over previous
#include <cuda_runtime.h>
#include <cuda_bf16.h>
#include <math_constants.h>
#include <cstdint>

#define BBATCH 64
#define LLEN   512
#define DDIM   512
#define AADIM  256
#define BL     (BBATCH * LLEN)   // 32768

// ---------------- scratch (__device__ globals) -------------------------------
__device__ __align__(256) __nv_bfloat16 g_S1h[(size_t)BL * DDIM];
__device__ __align__(256) __nv_bfloat16 g_S1l[(size_t)BL * DDIM];
__device__ __align__(256) __nv_bfloat16 g_S2h[(size_t)BL * DDIM];
__device__ __align__(256) __nv_bfloat16 g_S2l[(size_t)BL * DDIM];
__device__ __align__(256) __nv_bfloat16 g_Wth[(size_t)DDIM * DDIM];
__device__ __align__(256) __nv_bfloat16 g_Wtl[(size_t)DDIM * DDIM];
__device__ __align__(256) __nv_bfloat16 g_Wvth[(size_t)AADIM * DDIM];
__device__ __align__(256) __nv_bfloat16 g_Wvtl[(size_t)AADIM * DDIM];
__device__ __align__(256) __nv_bfloat16 g_Wqth[(size_t)AADIM * DDIM];
__device__ __align__(256) __nv_bfloat16 g_Wqtl[(size_t)AADIM * DDIM];
__device__ __align__(256) __nv_bfloat16 g_Th [(size_t)BL * DDIM];
__device__ __align__(256) __nv_bfloat16 g_Tl [(size_t)BL * DDIM];
__device__ __align__(256) __nv_bfloat16 g_Ch [(size_t)BBATCH * LLEN * LLEN];
__device__ __align__(256) __nv_bfloat16 g_Cl [(size_t)BBATCH * LLEN * LLEN];
__device__ __align__(256) __nv_bfloat16 g_CTh[(size_t)BBATCH * LLEN * LLEN];
__device__ __align__(256) __nv_bfloat16 g_CTl[(size_t)BBATCH * LLEN * LLEN];
__device__ __align__(256) __nv_bfloat16 g_Pth[(size_t)AADIM * BL];
__device__ __align__(256) __nv_bfloat16 g_Ptl[(size_t)AADIM * BL];
__device__ __align__(256) __nv_bfloat16 g_Qth[(size_t)AADIM * BL];
__device__ __align__(256) __nv_bfloat16 g_Qtl[(size_t)AADIM * BL];
__device__ __align__(256) float g_P [(size_t)BL * AADIM];
__device__ __align__(256) float g_Q [(size_t)BL * AADIM];
__device__ __align__(256) float g_Hv[(size_t)BL * AADIM];
__device__ __align__(256) float g_Hq[(size_t)BL * AADIM];

// ---------------- helpers -----------------------------------------------------
__device__ __forceinline__ uint32_t smem_u32(const void* p) {
    uint32_t a;
    asm("{ .reg .u64 t; cvta.to.shared.u64 t, %1; cvt.u32.u64 %0, t; }"
        : "=r"(a) : "l"(p));
    return a;
}
__device__ __forceinline__ uint32_t pk(__nv_bfloat16 a, __nv_bfloat16 b) {
    __nv_bfloat162 t = __halves2bfloat162(a, b);
    return *reinterpret_cast<uint32_t*>(&t);
}
__device__ __forceinline__ void split_f(float x, __nv_bfloat16& h, __nv_bfloat16& l) {
    h = __float2bfloat16(x);
    l = __float2bfloat16(x - __bfloat162float(h));
}

#define CP16(SM, G) \
    asm volatile("cp.async.cg.shared.global [%0], [%1], 16;" :: "r"(SM), "l"(G))
#define CP_COMMIT() asm volatile("cp.async.commit_group;")
#define CP_WAIT1()  asm volatile("cp.async.wait_group 1;")

#define LDSM4(R0,R1,R2,R3,ADDR) \
    asm volatile("ldmatrix.sync.aligned.m8n8.x4.shared.b16 {%0,%1,%2,%3}, [%4];" \
        : "=r"(R0),"=r"(R1),"=r"(R2),"=r"(R3) : "r"(ADDR))

__device__ __forceinline__ void mma_bf16(float* d, const uint32_t* a, const uint32_t* b) {
    asm volatile(
        "mma.sync.aligned.m16n8k16.row.col.f32.bf16.bf16.f32 "
        "{%0,%1,%2,%3}, {%4,%5,%6,%7}, {%8,%9}, {%0,%1,%2,%3};"
        : "+f"(d[0]), "+f"(d[1]), "+f"(d[2]), "+f"(d[3])
        : "r"(a[0]), "r"(a[1]), "r"(a[2]), "r"(a[3]), "r"(b[0]), "r"(b[1]));
}

// 64B-row swizzle: physical chunk = c ^ (r&3) ^ ((r>>2)&1); conflict-free for
// both cp.async 16B stores and ldmatrix 8-row reads.
__device__ __forceinline__ uint32_t swz64(int r, int ch) {
    return (uint32_t)(r * 64 + ((ch ^ (r & 3) ^ ((r >> 2) & 1)) << 4));
}

// stage layout per 32KB stage: AH 0 | AL 8K | BH 16K | BL2 24K  (128 rows x 32 k)
#define STG      32768
#define SM_BYTES 98304

// one bf16 tile: 128 rows x 32 K bf16 (64B/row); kc = 32-elem chunk index
__device__ __forceinline__ void stage32(uint32_t sdst, const __nv_bfloat16* src,
                                        int rowbase, int ld, int kc, int tid)
{
    #pragma unroll
    for (int q = 0; q < 2; q++) {
        int idx = tid + q * 256;
        int r = idx >> 2, c = idx & 3;
        uint32_t sa = sdst + swz64(r, c);
        const __nv_bfloat16* g = src + (size_t)(rowbase + r) * ld + kc * 32 + c * 8;
        CP16(sa, g);
    }
}

// ---------------- main MMA GEMM ------------------------------------------------
// CTA tile 128x128, 8 warps 2x4 (warp tile 64x32), 2 CTAs/SM. K in 16 chunks of 32.
// out[i][j] = sum_k A[i][k]*B[j][k]  (A,B: bf16 hi/lo, K-major, K=512)
// EPI 0: natural bf16 hi/lo [i][j]                                   (T)
// EPI 1: natural fp32 [i][j] + bounce-transposed bf16 hi/lo [j][i]   (P+Pt, Q+Qt)
// EPI 2: tanh; natural bf16 [i][j] + bounce bf16 [j][i]              (C, CT)
// EPI 3: tanh(acc + bias[i][j]); fp32 natural [i][j]                 (Hv, Hq)
template<int EPI>
__global__ void __launch_bounds__(256, 2)
gemm_mma(const __nv_bfloat16* __restrict__ Ah2, const __nv_bfloat16* __restrict__ Al2,
         size_t sA, int ldA,
         const __nv_bfloat16* __restrict__ Bh2, const __nv_bfloat16* __restrict__ Bl2,
         size_t sB, int ldB,
         const float* __restrict__ bias, size_t sBias, int ldBias,
         float* __restrict__ outF, size_t sF, int ldF,
         __nv_bfloat16* __restrict__ oh, __nv_bfloat16* __restrict__ ol,
         size_t sO, int ldO,
         __nv_bfloat16* __restrict__ th, __nv_bfloat16* __restrict__ tl,
         size_t sT, int ldT)
{
    extern __shared__ char smem[];
    const int tid  = threadIdx.x;
    const int lane = tid & 31, warp = tid >> 5;
    const int wm = warp >> 2, wn = warp & 3;   // 2 x 4 warp grid, warp tile 64x32
    const int z  = blockIdx.z;
    const int bi = blockIdx.x * 128, bj = blockIdx.y * 128;

    Ah2 += (size_t)z * sA;  Al2 += (size_t)z * sA;
    Bh2 += (size_t)z * sB;  Bl2 += (size_t)z * sB;
    if (EPI == 3) bias += (size_t)z * sBias;
    if (outF) outF += (size_t)z * sF;
    if (oh)   { oh += (size_t)z * sO; ol += (size_t)z * sO; }
    if (th)   { th += (size_t)z * sT; tl += (size_t)z * sT; }

    const uint32_t su = smem_u32(smem);

    float acc[4][4][4];
    #pragma unroll
    for (int a = 0; a < 4; a++)
        #pragma unroll
        for (int b = 0; b < 4; b++)
            #pragma unroll
            for (int c = 0; c < 4; c++) acc[a][b][c] = 0.f;

    const int arow_lo   = lane & 15;
    const int achunk_ad = lane >> 4;                      // 0/1: 16B chunk within k16
    const int gB        = lane >> 3;
    const int brow_lo   = ((gB >> 1) << 3) + (lane & 7);
    const int bchunk_ad = gB & 1;

    // prologue: stage chunks 0 and 1
    #pragma unroll
    for (int pc = 0; pc < 2; pc++) {
        uint32_t sb = su + pc * STG;
        stage32(sb,         Ah2, bi, ldA, pc, tid);
        stage32(sb +  8192, Al2, bi, ldA, pc, tid);
        stage32(sb + 16384, Bh2, bj, ldB, pc, tid);
        stage32(sb + 24576, Bl2, bj, ldB, pc, tid);
        CP_COMMIT();
    }

    #pragma unroll 1
    for (int c = 0; c < 16; c++) {
        CP_WAIT1();          // own copies of chunk c retired
        __syncthreads();     // everyone's chunk c visible; chunk c-1 readers done

        const uint32_t base = su + (c % 3) * STG;
        const uint32_t aB  = base;
        const uint32_t alB = base + 8192;
        const uint32_t bB  = base + 16384;
        const uint32_t blB = base + 24576;

        #pragma unroll
        for (int kb = 0; kb < 2; kb++) {       // two k16 steps per K32 chunk
            uint32_t ah[4][4], al[4][4];
            #pragma unroll
            for (int mi = 0; mi < 4; mi++) {
                int row = wm * 64 + mi * 16 + arow_lo;
                uint32_t off = swz64(row, kb * 2 + achunk_ad);
                LDSM4(ah[mi][0], ah[mi][1], ah[mi][2], ah[mi][3], aB  + off);
                LDSM4(al[mi][0], al[mi][1], al[mi][2], al[mi][3], alB + off);
            }
            #pragma unroll
            for (int ng = 0; ng < 2; ng++) {   // stream B frags to cap registers
                int row = wn * 32 + ng * 16 + brow_lo;
                uint32_t off = swz64(row, kb * 2 + bchunk_ad);
                uint32_t bh[2][2], blr[2][2];
                uint32_t t0, t1, t2, t3;
                LDSM4(t0, t1, t2, t3, bB + off);
                bh[0][0] = t0; bh[0][1] = t1; bh[1][0] = t2; bh[1][1] = t3;
                LDSM4(t0, t1, t2, t3, blB + off);
                blr[0][0] = t0; blr[0][1] = t1; blr[1][0] = t2; blr[1][1] = t3;
                #pragma unroll
                for (int mi = 0; mi < 4; mi++)
                    #pragma unroll
                    for (int nn = 0; nn < 2; nn++) {
                        int ni = ng * 2 + nn;
                        mma_bf16(acc[mi][ni], ah[mi], bh[nn]);
                        mma_bf16(acc[mi][ni], ah[mi], blr[nn]);
                        mma_bf16(acc[mi][ni], al[mi], bh[nn]);
                    }
            }
        }

        if (c + 2 < 16) {    // stage chunk c+2 into buffer (c+2)%3 = (c-1)%3 (safe)
            uint32_t sb = su + ((c + 2) % 3) * STG;
            stage32(sb,         Ah2, bi, ldA, c + 2, tid);
            stage32(sb +  8192, Al2, bi, ldA, c + 2, tid);
            stage32(sb + 16384, Bh2, bj, ldB, c + 2, tid);
            stage32(sb + 24576, Bl2, bj, ldB, c + 2, tid);
        }
        CP_COMMIT();         // unconditional: uniform group arithmetic
    }

    // ---------------- epilogue ----------------
    const int trow = lane >> 2;
    const int tcol = (lane & 3) * 2;

    if (EPI == 2 || EPI == 3) {
        #pragma unroll
        for (int mi = 0; mi < 4; mi++)
            #pragma unroll
            for (int ni = 0; ni < 4; ni++) {
                int j = bj + wn * 32 + ni * 8 + tcol;
                #pragma unroll
                for (int hf = 0; hf < 2; hf++) {
                    int i = bi + wm * 64 + mi * 16 + trow + hf * 8;
                    float x0 = acc[mi][ni][hf * 2 + 0];
                    float x1 = acc[mi][ni][hf * 2 + 1];
                    if (EPI == 3) {
                        float2 bv = *(const float2*)&bias[(size_t)i * ldBias + j];
                        x0 += bv.x; x1 += bv.y;
                    }
                    acc[mi][ni][hf * 2 + 0] = tanhf(x0);
                    acc[mi][ni][hf * 2 + 1] = tanhf(x1);
                }
            }
    }

    if (EPI == 0 || EPI == 2) {   // natural bf16 hi/lo stores [i][j]
        #pragma unroll
        for (int mi = 0; mi < 4; mi++)
            #pragma unroll
            for (int ni = 0; ni < 4; ni++) {
                int j = bj + wn * 32 + ni * 8 + tcol;
                #pragma unroll
                for (int hf = 0; hf < 2; hf++) {
                    int i = bi + wm * 64 + mi * 16 + trow + hf * 8;
                    float v0 = acc[mi][ni][hf * 2 + 0];
                    float v1 = acc[mi][ni][hf * 2 + 1];
                    __nv_bfloat16 h0, l0, h1, l1;
                    split_f(v0, h0, l0); split_f(v1, h1, l1);
                    *(uint32_t*)&oh[(size_t)i * ldO + j] = pk(h0, h1);
                    *(uint32_t*)&ol[(size_t)i * ldO + j] = pk(l0, l1);
                }
            }
    }

    if (EPI == 1 || EPI == 3) {   // natural fp32 stores [i][j]
        #pragma unroll
        for (int mi = 0; mi < 4; mi++)
            #pragma unroll
            for (int ni = 0; ni < 4; ni++) {
                int j = bj + wn * 32 + ni * 8 + tcol;
                #pragma unroll
                for (int hf = 0; hf < 2; hf++) {
                    int i = bi + wm * 64 + mi * 16 + trow + hf * 8;
                    float2 o;
                    o.x = acc[mi][ni][hf * 2 + 0];
                    o.y = acc[mi][ni][hf * 2 + 1];
                    *(float2*)&outF[(size_t)i * ldF + j] = o;
                }
            }
    }

    if (EPI == 1 || EPI == 2) {   // bounce-transposed bf16 hi/lo [j][i]
        float* smf = (float*)smem;   // 128 x 128, pitch 129 f32 (66KB <= 96KB)
        __syncthreads();             // stage ring dead; reuse
        #pragma unroll
        for (int mi = 0; mi < 4; mi++)
            #pragma unroll
            for (int ni = 0; ni < 4; ni++) {
                int jl = wn * 32 + ni * 8 + tcol;
                #pragma unroll
                for (int hf = 0; hf < 2; hf++) {
                    int il = wm * 64 + mi * 16 + trow + hf * 8;
                    smf[il * 129 + jl]     = acc[mi][ni][hf * 2 + 0];
                    smf[il * 129 + jl + 1] = acc[mi][ni][hf * 2 + 1];
                }
            }
        __syncthreads();
        const int ii0 = lane * 4;
        #pragma unroll 4
        for (int jrep = 0; jrep < 16; jrep++) {
            int jj = warp + jrep * 8;
            float v0 = smf[(ii0 + 0) * 129 + jj];
            float v1 = smf[(ii0 + 1) * 129 + jj];
            float v2 = smf[(ii0 + 2) * 129 + jj];
            float v3 = smf[(ii0 + 3) * 129 + jj];
            __nv_bfloat16 h0,l0,h1,l1,h2,l2,h3,l3;
            split_f(v0,h0,l0); split_f(v1,h1,l1); split_f(v2,h2,l2); split_f(v3,h3,l3);
            size_t base_o = (size_t)(bj + jj) * ldT + bi + ii0;
            *(uint2*)&th[base_o] = make_uint2(pk(h0,h1), pk(h2,h3));
            *(uint2*)&tl[base_o] = make_uint2(pk(l0,l1), pk(l2,l3));
        }
    }
}

// ---------------- prep kernels -------------------------------------------------
__global__ void __launch_bounds__(256)
split_k(const float4* __restrict__ in, uint2* __restrict__ hi, uint2* __restrict__ lo, int n4)
{
    int i = blockIdx.x * 256 + threadIdx.x;
    if (i >= n4) return;
    float4 v = in[i];
    __nv_bfloat16 h0,h1,h2,h3,l0,l1,l2,l3;
    split_f(v.x,h0,l0); split_f(v.y,h1,l1); split_f(v.z,h2,l2); split_f(v.w,h3,l3);
    hi[i] = make_uint2(pk(h0,h1), pk(h2,h3));
    lo[i] = make_uint2(pk(l0,l1), pk(l2,l3));
}

__global__ void __launch_bounds__(256)
tsplit_k(const float* __restrict__ in, int R, int C,
         __nv_bfloat16* __restrict__ oh, __nv_bfloat16* __restrict__ ol)
{
    __shared__ float t[32][33];
    int bx = blockIdx.x * 32, by = blockIdx.y * 32;
    int tx = threadIdx.x & 31, ty = threadIdx.x >> 5;
    #pragma unroll
    for (int i = 0; i < 32; i += 8)
        t[ty + i][tx] = in[(size_t)(by + ty + i) * C + bx + tx];
    __syncthreads();
    #pragma unroll
    for (int i = 0; i < 32; i += 8) {
        float v = t[tx][ty + i];
        __nv_bfloat16 h, l; split_f(v, h, l);
        oh[(size_t)(bx + ty + i) * R + by + tx] = h;
        ol[(size_t)(bx + ty + i) * R + by + tx] = l;
    }
}

// ---------------- masked softmax + pooling --------------------------------------
__device__ __forceinline__ float block_sum(float v, float* red) {
    int lane = threadIdx.x & 31, warp = threadIdx.x >> 5;
    #pragma unroll
    for (int o = 16; o; o >>= 1) v += __shfl_xor_sync(0xffffffffu, v, o);
    if (lane == 0) red[warp] = v;
    __syncthreads();
    float t = 0.f;
    #pragma unroll
    for (int i = 0; i < 8; i++) t += red[i];
    __syncthreads();
    return t;
}
__device__ __forceinline__ float block_max(float v, float* red) {
    int lane = threadIdx.x & 31, warp = threadIdx.x >> 5;
    #pragma unroll
    for (int o = 16; o; o >>= 1) v = fmaxf(v, __shfl_xor_sync(0xffffffffu, v, o));
    if (lane == 0) red[warp] = v;
    __syncthreads();
    float t = red[0];
    #pragma unroll
    for (int i = 1; i < 8; i++) t = fmaxf(t, red[i]);
    __syncthreads();
    return t;
}

__global__ void __launch_bounds__(256)
attn_pool_k(const float* __restrict__ H, const float* __restrict__ w,
            const int* __restrict__ mask, const float* __restrict__ X,
            float* __restrict__ out)
{
    __shared__ float sw[AADIM];
    __shared__ float sl[LLEN];
    __shared__ float smk[LLEN];
    __shared__ float red[8];

    const int b = blockIdx.x;
    const int tid = threadIdx.x;
    const int lane = tid & 31, warp = tid >> 5;

    for (int a = tid; a < AADIM; a += 256) sw[a] = w[a];
    for (int l = tid; l < LLEN; l += 256) smk[l] = (float)mask[b * LLEN + l];
    __syncthreads();

    for (int l = warp; l < LLEN; l += 8) {
        const float* Hr = H + ((size_t)b * LLEN + l) * AADIM;
        float s = 0.f;
        #pragma unroll
        for (int a = lane; a < AADIM; a += 32) s = fmaf(Hr[a], sw[a], s);
        #pragma unroll
        for (int o = 16; o; o >>= 1) s += __shfl_down_sync(0xffffffffu, s, o);
        if (lane == 0) sl[l] = s * smk[l];
    }
    __syncthreads();

    float m = -CUDART_INF_F;
    for (int l = tid; l < LLEN; l += 256) m = fmaxf(m, sl[l]);
    m = block_max(m, red);

    float psum = 0.f;
    for (int l = tid; l < LLEN; l += 256) {
        float e = expf(sl[l] - m);
        sl[l] = e; psum += e;
    }
    psum = block_sum(psum, red);
    float inv = 1.f / psum;

    float rsum = 0.f;
    for (int l = tid; l < LLEN; l += 256) {
        float r = sl[l] * inv * smk[l];
        sl[l] = r; rsum += r;
    }
    rsum = block_sum(rsum, red);
    float sc = 1.f / (rsum + 1e-13f);
    for (int l = tid; l < LLEN; l += 256) sl[l] *= sc;
    __syncthreads();

    for (int d = tid; d < DDIM; d += 256) {
        const float* Xb = X + (size_t)b * LLEN * DDIM + d;
        float acc = 0.f;
        #pragma unroll 4
        for (int l = 0; l < LLEN; l++) acc = fmaf(sl[l], Xb[(size_t)l * DDIM], acc);
        out[(size_t)b * DDIM + d] = acc;
    }
}

// ---------------- launch ---------------------------------------------------------
extern "C" void kernel_launch(void* const* d_in, const int* in_sizes, int n_in,
                              void* d_out, int out_size)
{
    const float* S1    = (const float*)d_in[0];
    const float* S2    = (const float*)d_in[1];
    const int*   mask1 = (const int*)  d_in[2];
    const int*   mask2 = (const int*)  d_in[3];
    const float* W     = (const float*)d_in[4];
    const float* Wv    = (const float*)d_in[5];
    const float* Wq    = (const float*)d_in[6];
    const float* w_hv  = (const float*)d_in[7];
    const float* w_hq  = (const float*)d_in[8];
    float* out = (float*)d_out;

    __nv_bfloat16 *S1h,*S1l,*S2h,*S2l,*Wth,*Wtl,*Wvth,*Wvtl,*Wqth,*Wqtl;
    __nv_bfloat16 *Th,*Tl,*Ch,*Cl,*CTh,*CTl,*Pth,*Ptl,*Qth,*Qtl;
    float *P,*Q,*Hv,*Hq;
    cudaGetSymbolAddress((void**)&S1h, g_S1h);  cudaGetSymbolAddress((void**)&S1l, g_S1l);
    cudaGetSymbolAddress((void**)&S2h, g_S2h);  cudaGetSymbolAddress((void**)&S2l, g_S2l);
    cudaGetSymbolAddress((void**)&Wth, g_Wth);  cudaGetSymbolAddress((void**)&Wtl, g_Wtl);
    cudaGetSymbolAddress((void**)&Wvth,g_Wvth); cudaGetSymbolAddress((void**)&Wvtl,g_Wvtl);
    cudaGetSymbolAddress((void**)&Wqth,g_Wqth); cudaGetSymbolAddress((void**)&Wqtl,g_Wqtl);
    cudaGetSymbolAddress((void**)&Th,  g_Th);   cudaGetSymbolAddress((void**)&Tl,  g_Tl);
    cudaGetSymbolAddress((void**)&Ch,  g_Ch);   cudaGetSymbolAddress((void**)&Cl,  g_Cl);
    cudaGetSymbolAddress((void**)&CTh, g_CTh);  cudaGetSymbolAddress((void**)&CTl, g_CTl);
    cudaGetSymbolAddress((void**)&Pth, g_Pth);  cudaGetSymbolAddress((void**)&Ptl, g_Ptl);
    cudaGetSymbolAddress((void**)&Qth, g_Qth);  cudaGetSymbolAddress((void**)&Qtl, g_Qtl);
    cudaGetSymbolAddress((void**)&P,   g_P);    cudaGetSymbolAddress((void**)&Q,   g_Q);
    cudaGetSymbolAddress((void**)&Hv,  g_Hv);   cudaGetSymbolAddress((void**)&Hq,  g_Hq);

    cudaFuncSetAttribute(gemm_mma<0>, cudaFuncAttributeMaxDynamicSharedMemorySize, SM_BYTES);
    cudaFuncSetAttribute(gemm_mma<1>, cudaFuncAttributeMaxDynamicSharedMemorySize, SM_BYTES);
    cudaFuncSetAttribute(gemm_mma<2>, cudaFuncAttributeMaxDynamicSharedMemorySize, SM_BYTES);
    cudaFuncSetAttribute(gemm_mma<3>, cudaFuncAttributeMaxDynamicSharedMemorySize, SM_BYTES);

    const dim3 blk(256);
    const size_t sLL = (size_t)LLEN * LLEN;
    const size_t sLA = (size_t)LLEN * AADIM;
    const size_t sLD = (size_t)LLEN * DDIM;

    split_k<<<(BL * DDIM / 4 + 255) / 256, blk>>>((const float4*)S1, (uint2*)S1h, (uint2*)S1l, BL * DDIM / 4);
    split_k<<<(BL * DDIM / 4 + 255) / 256, blk>>>((const float4*)S2, (uint2*)S2h, (uint2*)S2l, BL * DDIM / 4);
    tsplit_k<<<dim3(DDIM / 32, DDIM / 32), blk>>>(W,  DDIM, DDIM,  Wth,  Wtl);
    tsplit_k<<<dim3(AADIM / 32, DDIM / 32), blk>>>(Wv, DDIM, AADIM, Wvth, Wvtl);
    tsplit_k<<<dim3(AADIM / 32, DDIM / 32), blk>>>(Wq, DDIM, AADIM, Wqth, Wqtl);

    // G1: T = S1 @ W.  i=l (BL), j=d. EPI0 -> Th/Tl [l][d].
    gemm_mma<0><<<dim3(BL/128, DDIM/128, 1), blk, SM_BYTES>>>(
        S1h, S1l, 0, DDIM,  Wth, Wtl, 0, DDIM,
        nullptr, 0, 0,  nullptr, 0, 0,
        Th, Tl, 0, DDIM,  nullptr, nullptr, 0, 0);

    // G2: i=l, j=a. EPI1 -> P fp32 [l][a] + Pt bf16 [a][BL].
    gemm_mma<1><<<dim3(BL/128, AADIM/128, 1), blk, SM_BYTES>>>(
        S1h, S1l, 0, DDIM,  Wvth, Wvtl, 0, DDIM,
        nullptr, 0, 0,  P, 0, AADIM,
        nullptr, nullptr, 0, 0,  Pth, Ptl, 0, BL);

    // G3: -> Q fp32 [l][a] + Qt bf16 [a][BL].
    gemm_mma<1><<<dim3(BL/128, AADIM/128, 1), blk, SM_BYTES>>>(
        S2h, S2l, 0, DDIM,  Wqth, Wqtl, 0, DDIM,
        nullptr, 0, 0,  Q, 0, AADIM,
        nullptr, nullptr, 0, 0,  Qth, Qtl, 0, BL);

    // G4: C = tanh(T @ S2^T). i=l1, j=l2, batched. EPI2 -> C [l1][l2] + CT [l2][l1].
    gemm_mma<2><<<dim3(LLEN/128, LLEN/128, BBATCH), blk, SM_BYTES>>>(
        Th, Tl, sLD, DDIM,  S2h, S2l, sLD, DDIM,
        nullptr, 0, 0,  nullptr, 0, 0,
        Ch, Cl, sLL, LLEN,  CTh, CTl, sLL, LLEN);

    // G5: Hv = tanh(P + C @ Q). i=l1, j=a. B = Qt (ld BL, batch offset z*LLEN).
    gemm_mma<3><<<dim3(LLEN/128, AADIM/128, BBATCH), blk, SM_BYTES>>>(
        Ch, Cl, sLL, LLEN,  Qth, Qtl, (size_t)LLEN, BL,
        P, sLA, AADIM,  Hv, sLA, AADIM,
        nullptr, nullptr, 0, 0,  nullptr, nullptr, 0, 0);

    // G6: Hq = tanh(Q + C^T @ P). i=l2, j=a. B = Pt.
    gemm_mma<3><<<dim3(LLEN/128, AADIM/128, BBATCH), blk, SM_BYTES>>>(
        CTh, CTl, sLL, LLEN,  Pth, Ptl, (size_t)LLEN, BL,
        Q, sLA, AADIM,  Hq, sLA, AADIM,
        nullptr, nullptr, 0, 0,  nullptr, nullptr, 0, 0);

    attn_pool_k<<<BBATCH, blk>>>(Hv, w_hv, mask1, S1, out);
    attn_pool_k<<<BBATCH, blk>>>(Hq, w_hq, mask2, S2, out + (size_t)BBATCH * DDIM);
}

// round 10
// speedup vs baseline: 2.5686x; 1.2558x over previous
#include <cuda_runtime.h>
#include <cuda_bf16.h>
#include <math_constants.h>
#include <cstdint>

#define BBATCH 64
#define LLEN   512
#define DDIM   512
#define AADIM  256
#define BL     (BBATCH * LLEN)

__device__ __align__(256) __nv_bfloat16 g_S1h[(size_t)BL * DDIM];
__device__ __align__(256) __nv_bfloat16 g_S1l[(size_t)BL * DDIM];
__device__ __align__(256) __nv_bfloat16 g_S2h[(size_t)BL * DDIM];
__device__ __align__(256) __nv_bfloat16 g_S2l[(size_t)BL * DDIM];
__device__ __align__(256) __nv_bfloat16 g_Wth[(size_t)DDIM * DDIM];
__device__ __align__(256) __nv_bfloat16 g_Wtl[(size_t)DDIM * DDIM];
__device__ __align__(256) __nv_bfloat16 g_Wvth[(size_t)AADIM * DDIM];
__device__ __align__(256) __nv_bfloat16 g_Wvtl[(size_t)AADIM * DDIM];
__device__ __align__(256) __nv_bfloat16 g_Wqth[(size_t)AADIM * DDIM];
__device__ __align__(256) __nv_bfloat16 g_Wqtl[(size_t)AADIM * DDIM];
__device__ __align__(256) __nv_bfloat16 g_Th [(size_t)BL * DDIM];
__device__ __align__(256) __nv_bfloat16 g_Tl [(size_t)BL * DDIM];
__device__ __align__(256) __nv_bfloat16 g_Ch [(size_t)BBATCH * LLEN * LLEN];
__device__ __align__(256) __nv_bfloat16 g_Cl [(size_t)BBATCH * LLEN * LLEN];
__device__ __align__(256) __nv_bfloat16 g_CTh[(size_t)BBATCH * LLEN * LLEN];
__device__ __align__(256) __nv_bfloat16 g_CTl[(size_t)BBATCH * LLEN * LLEN];
__device__ __align__(256) __nv_bfloat16 g_Pth[(size_t)AADIM * BL];
__device__ __align__(256) __nv_bfloat16 g_Ptl[(size_t)AADIM * BL];
__device__ __align__(256) __nv_bfloat16 g_Qth[(size_t)AADIM * BL];
__device__ __align__(256) __nv_bfloat16 g_Qtl[(size_t)AADIM * BL];
__device__ __align__(256) float g_P [(size_t)BL * AADIM];
__device__ __align__(256) float g_Q [(size_t)BL * AADIM];
__device__ __align__(256) float g_Hv[(size_t)BL * AADIM];
__device__ __align__(256) float g_Hq[(size_t)BL * AADIM];

__device__ __forceinline__ uint32_t smem_u32(const void* p) {
    uint32_t a;
    asm("{ .reg .u64 t; cvta.to.shared.u64 t, %1; cvt.u32.u64 %0, t; }"
        : "=r"(a) : "l"(p));
    return a;
}
__device__ __forceinline__ uint32_t pk(__nv_bfloat16 a, __nv_bfloat16 b) {
    __nv_bfloat162 t = __halves2bfloat162(a, b);
    return *reinterpret_cast<uint32_t*>(&t);
}
__device__ __forceinline__ void split_f(float x, __nv_bfloat16& h, __nv_bfloat16& l) {
    h = __float2bfloat16(x);
    l = __float2bfloat16(x - __bfloat162float(h));
}

#define CP16(SM, G) \
    asm volatile("cp.async.cg.shared.global [%0], [%1], 16;" :: "r"(SM), "l"(G))
#define CP_COMMIT() asm volatile("cp.async.commit_group;")
#define CP_WAIT1()  asm volatile("cp.async.wait_group 1;")

#define LDSM4(R0,R1,R2,R3,ADDR) \
    asm volatile("ldmatrix.sync.aligned.m8n8.x4.shared.b16 {%0,%1,%2,%3}, [%4];" \
        : "=r"(R0),"=r"(R1),"=r"(R2),"=r"(R3) : "r"(ADDR))

__device__ __forceinline__ void mma_bf16(float* d, const uint32_t* a, const uint32_t* b) {
    asm volatile(
        "mma.sync.aligned.m16n8k16.row.col.f32.bf16.bf16.f32 "
        "{%0,%1,%2,%3}, {%4,%5,%6,%7}, {%8,%9}, {%0,%1,%2,%3};"
        : "+f"(d[0]), "+f"(d[1]), "+f"(d[2]), "+f"(d[3])
        : "r"(a[0]), "r"(a[1]), "r"(a[2]), "r"(a[3]), "r"(b[0]), "r"(b[1]));
}

__device__ __forceinline__ uint32_t swz64(int r, int ch) {
    return (uint32_t)(r * 64 + ((ch ^ (r & 3) ^ ((r >> 2) & 1)) << 4));
}

#define STG      32768
#define SM_BYTES 98304

__device__ __forceinline__ void stage32(uint32_t sdst, const __nv_bfloat16* src,
                                        int rowbase, int ld, int kc, int tid)
{
    #pragma unroll
    for (int q = 0; q < 2; q++) {
        int idx = tid + q * 256;
        int r = idx >> 2, c = idx & 3;
        uint32_t sa = sdst + swz64(r, c);
        const __nv_bfloat16* g = src + (size_t)(rowbase + r) * ld + kc * 32 + c * 8;
        CP16(sa, g);
    }
}

// ---------------- GEMM parameter block + body -----------------------------------
struct GArgs {
    const __nv_bfloat16 *Ah, *Al, *Bh, *Bl;
    size_t sA, sB; int ldA, ldB;
    const float* bias; size_t sBias; int ldBias;
    float* outF; size_t sF; int ldF;
    __nv_bfloat16 *oh, *ol; size_t sO; int ldO;
    __nv_bfloat16 *th, *tl; size_t sT; int ldT;
};

// CTA tile 128x128, 8 warps 2x4 (warp 64x32), 2 CTAs/SM. K=512 in 16 chunks of 32.
// EPI 0: natural bf16 h/l [i][j]                 (T)
// EPI 1: natural fp32 [i][j] + bounce bf16 [j][i] (P+Pt, Q+Qt)
// EPI 2: tanh; natural bf16 + bounce bf16         (C, CT)
// EPI 3: tanh(acc+bias); fp32 natural             (Hv, Hq)
template<int EPI>
__device__ __forceinline__ void gemm_body(const GArgs& G, char* smem,
                                          int bi, int bj, int z)
{
    const int tid  = threadIdx.x;
    const int lane = tid & 31, warp = tid >> 5;
    const int wm = warp >> 2, wn = warp & 3;

    const __nv_bfloat16* Ah2 = G.Ah + (size_t)z * G.sA;
    const __nv_bfloat16* Al2 = G.Al + (size_t)z * G.sA;
    const __nv_bfloat16* Bh2 = G.Bh + (size_t)z * G.sB;
    const __nv_bfloat16* Bl2 = G.Bl + (size_t)z * G.sB;
    const int ldA = G.ldA, ldB = G.ldB;

    const uint32_t su = smem_u32(smem);

    float acc[4][4][4];
    #pragma unroll
    for (int a = 0; a < 4; a++)
        #pragma unroll
        for (int b = 0; b < 4; b++)
            #pragma unroll
            for (int c = 0; c < 4; c++) acc[a][b][c] = 0.f;

    const int arow_lo   = lane & 15;
    const int achunk_ad = lane >> 4;
    const int gB        = lane >> 3;
    const int brow_lo   = ((gB >> 1) << 3) + (lane & 7);
    const int bchunk_ad = gB & 1;

    #pragma unroll
    for (int pc = 0; pc < 2; pc++) {
        uint32_t sb = su + pc * STG;
        stage32(sb,         Ah2, bi, ldA, pc, tid);
        stage32(sb +  8192, Al2, bi, ldA, pc, tid);
        stage32(sb + 16384, Bh2, bj, ldB, pc, tid);
        stage32(sb + 24576, Bl2, bj, ldB, pc, tid);
        CP_COMMIT();
    }

    #pragma unroll 1
    for (int c = 0; c < 16; c++) {
        CP_WAIT1();
        __syncthreads();

        const uint32_t base = su + (c % 3) * STG;
        const uint32_t aB  = base;
        const uint32_t alB = base + 8192;
        const uint32_t bB  = base + 16384;
        const uint32_t blB = base + 24576;

        #pragma unroll
        for (int kb = 0; kb < 2; kb++) {
            uint32_t ah[4][4], al[4][4];
            #pragma unroll
            for (int mi = 0; mi < 4; mi++) {
                int row = wm * 64 + mi * 16 + arow_lo;
                uint32_t off = swz64(row, kb * 2 + achunk_ad);
                LDSM4(ah[mi][0], ah[mi][1], ah[mi][2], ah[mi][3], aB  + off);
                LDSM4(al[mi][0], al[mi][1], al[mi][2], al[mi][3], alB + off);
            }
            #pragma unroll
            for (int ng = 0; ng < 2; ng++) {
                int row = wn * 32 + ng * 16 + brow_lo;
                uint32_t off = swz64(row, kb * 2 + bchunk_ad);
                uint32_t bh[2][2], blr[2][2];
                uint32_t t0, t1, t2, t3;
                LDSM4(t0, t1, t2, t3, bB + off);
                bh[0][0] = t0; bh[0][1] = t1; bh[1][0] = t2; bh[1][1] = t3;
                LDSM4(t0, t1, t2, t3, blB + off);
                blr[0][0] = t0; blr[0][1] = t1; blr[1][0] = t2; blr[1][1] = t3;
                #pragma unroll
                for (int mi = 0; mi < 4; mi++)
                    #pragma unroll
                    for (int nn = 0; nn < 2; nn++) {
                        int ni = ng * 2 + nn;
                        mma_bf16(acc[mi][ni], ah[mi], bh[nn]);
                        mma_bf16(acc[mi][ni], ah[mi], blr[nn]);
                        mma_bf16(acc[mi][ni], al[mi], bh[nn]);
                    }
            }
        }

        if (c + 2 < 16) {
            uint32_t sb = su + ((c + 2) % 3) * STG;
            stage32(sb,         Ah2, bi, ldA, c + 2, tid);
            stage32(sb +  8192, Al2, bi, ldA, c + 2, tid);
            stage32(sb + 16384, Bh2, bj, ldB, c + 2, tid);
            stage32(sb + 24576, Bl2, bj, ldB, c + 2, tid);
        }
        CP_COMMIT();
    }

    // ---- epilogue ----
    const int trow = lane >> 2;
    const int tcol = (lane & 3) * 2;

    const float* bias = (EPI == 3) ? G.bias + (size_t)z * G.sBias : nullptr;
    float* outF = G.outF ? G.outF + (size_t)z * G.sF : nullptr;
    __nv_bfloat16* oh = G.oh ? G.oh + (size_t)z * G.sO : nullptr;
    __nv_bfloat16* ol = G.ol ? G.ol + (size_t)z * G.sO : nullptr;
    __nv_bfloat16* th = G.th ? G.th + (size_t)z * G.sT : nullptr;
    __nv_bfloat16* tl = G.tl ? G.tl + (size_t)z * G.sT : nullptr;

    if (EPI == 2 || EPI == 3) {
        #pragma unroll
        for (int mi = 0; mi < 4; mi++)
            #pragma unroll
            for (int ni = 0; ni < 4; ni++) {
                int j = bj + wn * 32 + ni * 8 + tcol;
                #pragma unroll
                for (int hf = 0; hf < 2; hf++) {
                    int i = bi + wm * 64 + mi * 16 + trow + hf * 8;
                    float x0 = acc[mi][ni][hf * 2 + 0];
                    float x1 = acc[mi][ni][hf * 2 + 1];
                    if (EPI == 3) {
                        float2 bv = *(const float2*)&bias[(size_t)i * G.ldBias + j];
                        x0 += bv.x; x1 += bv.y;
                    }
                    acc[mi][ni][hf * 2 + 0] = tanhf(x0);
                    acc[mi][ni][hf * 2 + 1] = tanhf(x1);
                }
            }
    }

    if (EPI == 0 || EPI == 2) {
        #pragma unroll
        for (int mi = 0; mi < 4; mi++)
            #pragma unroll
            for (int ni = 0; ni < 4; ni++) {
                int j = bj + wn * 32 + ni * 8 + tcol;
                #pragma unroll
                for (int hf = 0; hf < 2; hf++) {
                    int i = bi + wm * 64 + mi * 16 + trow + hf * 8;
                    float v0 = acc[mi][ni][hf * 2 + 0];
                    float v1 = acc[mi][ni][hf * 2 + 1];
                    __nv_bfloat16 h0, l0, h1, l1;
                    split_f(v0, h0, l0); split_f(v1, h1, l1);
                    *(uint32_t*)&oh[(size_t)i * G.ldO + j] = pk(h0, h1);
                    *(uint32_t*)&ol[(size_t)i * G.ldO + j] = pk(l0, l1);
                }
            }
    }

    if (EPI == 1 || EPI == 3) {
        #pragma unroll
        for (int mi = 0; mi < 4; mi++)
            #pragma unroll
            for (int ni = 0; ni < 4; ni++) {
                int j = bj + wn * 32 + ni * 8 + tcol;
                #pragma unroll
                for (int hf = 0; hf < 2; hf++) {
                    int i = bi + wm * 64 + mi * 16 + trow + hf * 8;
                    float2 o;
                    o.x = acc[mi][ni][hf * 2 + 0];
                    o.y = acc[mi][ni][hf * 2 + 1];
                    *(float2*)&outF[(size_t)i * G.ldF + j] = o;
                }
            }
    }

    if (EPI == 1 || EPI == 2) {   // bounce-transposed bf16 h/l [j][i]
        float* smf = (float*)smem;
        __syncthreads();
        #pragma unroll
        for (int mi = 0; mi < 4; mi++)
            #pragma unroll
            for (int ni = 0; ni < 4; ni++) {
                int jl = wn * 32 + ni * 8 + tcol;
                #pragma unroll
                for (int hf = 0; hf < 2; hf++) {
                    int il = wm * 64 + mi * 16 + trow + hf * 8;
                    smf[il * 129 + jl]     = acc[mi][ni][hf * 2 + 0];
                    smf[il * 129 + jl + 1] = acc[mi][ni][hf * 2 + 1];
                }
            }
        __syncthreads();
        const int ii0 = lane * 4;
        #pragma unroll 4
        for (int jrep = 0; jrep < 16; jrep++) {
            int jj = warp + jrep * 8;
            float v0 = smf[(ii0 + 0) * 129 + jj];
            float v1 = smf[(ii0 + 1) * 129 + jj];
            float v2 = smf[(ii0 + 2) * 129 + jj];
            float v3 = smf[(ii0 + 3) * 129 + jj];
            __nv_bfloat16 h0,l0,h1,l1,h2,l2,h3,l3;
            split_f(v0,h0,l0); split_f(v1,h1,l1); split_f(v2,h2,l2); split_f(v3,h3,l3);
            size_t base_o = (size_t)(bj + jj) * G.ldT + bi + ii0;
            *(uint2*)&th[base_o] = make_uint2(pk(h0,h1), pk(h2,h3));
            *(uint2*)&tl[base_o] = make_uint2(pk(l0,l1), pk(l2,l3));
        }
    }
}

// ---------------- merged GEMM kernels -------------------------------------------
// G1 (z<4), G2 (z=4,5), G3 (z=6,7); grid (256, 1, 8)
__global__ void __launch_bounds__(256, 2)
mega123(GArgs g1, GArgs g2, GArgs g3)
{
    extern __shared__ char smem[];
    int z = blockIdx.z, bi = blockIdx.x * 128;
    if (z < 4)      gemm_body<0>(g1, smem, bi, z * 128, 0);
    else if (z < 6) gemm_body<1>(g2, smem, bi, (z - 4) * 128, 0);
    else            gemm_body<1>(g3, smem, bi, (z - 6) * 128, 0);
}

// G4: grid (4, 4, 64)
__global__ void __launch_bounds__(256, 2)
gemm4(GArgs g)
{
    extern __shared__ char smem[];
    gemm_body<2>(g, smem, blockIdx.x * 128, blockIdx.y * 128, blockIdx.z);
}

// G5 (z<64), G6 (z>=64): grid (4, 2, 128)
__global__ void __launch_bounds__(256, 2)
mega56(GArgs g5, GArgs g6)
{
    extern __shared__ char smem[];
    int z = blockIdx.z, bi = blockIdx.x * 128, bj = blockIdx.y * 128;
    if (z < 64) gemm_body<3>(g5, smem, bi, bj, z);
    else        gemm_body<3>(g6, smem, bi, bj, z - 64);
}

// ---------------- prep kernels ---------------------------------------------------
__global__ void __launch_bounds__(256)
split_both(const float4* __restrict__ s1, uint2* h1, uint2* l1,
           const float4* __restrict__ s2, uint2* h2, uint2* l2, int n4)
{
    int i = blockIdx.x * 256 + threadIdx.x;
    if (i >= 2 * n4) return;
    const float4* in = (i < n4) ? s1 : s2;
    uint2 *hi = (i < n4) ? h1 : h2, *lo = (i < n4) ? l1 : l2;
    int k = (i < n4) ? i : i - n4;
    float4 v = in[k];
    __nv_bfloat16 h0,h1_,h2_,h3,l0,l1_,l2_,l3;
    split_f(v.x,h0,l0); split_f(v.y,h1_,l1_); split_f(v.z,h2_,l2_); split_f(v.w,h3,l3);
    hi[k] = make_uint2(pk(h0,h1_), pk(h2_,h3));
    lo[k] = make_uint2(pk(l0,l1_), pk(l2_,l3));
}

__device__ __forceinline__ void tsplit_tile(const float* in, int R, int C,
                                            __nv_bfloat16* oh, __nv_bfloat16* ol,
                                            int bx, int by)
{
    __shared__ float t[32][33];
    int tx = threadIdx.x & 31, ty = threadIdx.x >> 5;
    #pragma unroll
    for (int i = 0; i < 32; i += 8)
        t[ty + i][tx] = in[(size_t)(by + ty + i) * C + bx + tx];
    __syncthreads();
    #pragma unroll
    for (int i = 0; i < 32; i += 8) {
        float v = t[tx][ty + i];
        __nv_bfloat16 h, l; split_f(v, h, l);
        oh[(size_t)(bx + ty + i) * R + by + tx] = h;
        ol[(size_t)(bx + ty + i) * R + by + tx] = l;
    }
}

// W: 256 tiles (16x16); Wv: 128 (8x16); Wq: 128 (8x16). grid 512.
__global__ void __launch_bounds__(256)
tsplit_all(const float* W, __nv_bfloat16* Wth, __nv_bfloat16* Wtl,
           const float* Wv, __nv_bfloat16* Wvth, __nv_bfloat16* Wvtl,
           const float* Wq, __nv_bfloat16* Wqth, __nv_bfloat16* Wqtl)
{
    int b = blockIdx.x;
    if (b < 256)      tsplit_tile(W,  DDIM, DDIM,  Wth,  Wtl,  (b & 15) * 32, (b >> 4) * 32);
    else if (b < 384) { b -= 256; tsplit_tile(Wv, DDIM, AADIM, Wvth, Wvtl, (b & 7) * 32, (b >> 3) * 32); }
    else              { b -= 384; tsplit_tile(Wq, DDIM, AADIM, Wqth, Wqtl, (b & 7) * 32, (b >> 3) * 32); }
}

// ---------------- masked softmax + pooling ---------------------------------------
__device__ __forceinline__ float block_sum(float v, float* red) {
    int lane = threadIdx.x & 31, warp = threadIdx.x >> 5;
    #pragma unroll
    for (int o = 16; o; o >>= 1) v += __shfl_xor_sync(0xffffffffu, v, o);
    if (lane == 0) red[warp] = v;
    __syncthreads();
    float t = 0.f;
    #pragma unroll
    for (int i = 0; i < 8; i++) t += red[i];
    __syncthreads();
    return t;
}
__device__ __forceinline__ float block_max(float v, float* red) {
    int lane = threadIdx.x & 31, warp = threadIdx.x >> 5;
    #pragma unroll
    for (int o = 16; o; o >>= 1) v = fmaxf(v, __shfl_xor_sync(0xffffffffu, v, o));
    if (lane == 0) red[warp] = v;
    __syncthreads();
    float t = red[0];
    #pragma unroll
    for (int i = 1; i < 8; i++) t = fmaxf(t, red[i]);
    __syncthreads();
    return t;
}

__global__ void __launch_bounds__(256)
attn_pool2(const float* __restrict__ Hv, const float* __restrict__ whv,
           const int* __restrict__ m1, const float* __restrict__ S1,
           const float* __restrict__ Hq, const float* __restrict__ whq,
           const int* __restrict__ m2, const float* __restrict__ S2,
           float* __restrict__ out)
{
    __shared__ float sw[AADIM];
    __shared__ float sl[LLEN];
    __shared__ float smk[LLEN];
    __shared__ float red[8];

    const int sel = blockIdx.x >> 6;
    const int b   = blockIdx.x & 63;
    const float* H = sel ? Hq : Hv;
    const float* w = sel ? whq : whv;
    const int* mask = sel ? m2 : m1;
    const float* X = sel ? S2 : S1;
    float* o = out + (size_t)sel * BBATCH * DDIM;

    const int tid = threadIdx.x;
    const int lane = tid & 31, warp = tid >> 5;

    for (int a = tid; a < AADIM; a += 256) sw[a] = w[a];
    for (int l = tid; l < LLEN; l += 256) smk[l] = (float)mask[b * LLEN + l];
    __syncthreads();

    for (int l = warp; l < LLEN; l += 8) {
        const float* Hr = H + ((size_t)b * LLEN + l) * AADIM;
        float s = 0.f;
        #pragma unroll
        for (int a = lane; a < AADIM; a += 32) s = fmaf(Hr[a], sw[a], s);
        #pragma unroll
        for (int o2 = 16; o2; o2 >>= 1) s += __shfl_down_sync(0xffffffffu, s, o2);
        if (lane == 0) sl[l] = s * smk[l];
    }
    __syncthreads();

    float m = -CUDART_INF_F;
    for (int l = tid; l < LLEN; l += 256) m = fmaxf(m, sl[l]);
    m = block_max(m, red);

    float psum = 0.f;
    for (int l = tid; l < LLEN; l += 256) {
        float e = expf(sl[l] - m);
        sl[l] = e; psum += e;
    }
    psum = block_sum(psum, red);
    float inv = 1.f / psum;

    float rsum = 0.f;
    for (int l = tid; l < LLEN; l += 256) {
        float r = sl[l] * inv * smk[l];
        sl[l] = r; rsum += r;
    }
    rsum = block_sum(rsum, red);
    float sc = 1.f / (rsum + 1e-13f);
    for (int l = tid; l < LLEN; l += 256) sl[l] *= sc;
    __syncthreads();

    for (int d = tid; d < DDIM; d += 256) {
        const float* Xb = X + (size_t)b * LLEN * DDIM + d;
        float acc = 0.f;
        #pragma unroll 4
        for (int l = 0; l < LLEN; l++) acc = fmaf(sl[l], Xb[(size_t)l * DDIM], acc);
        o[(size_t)b * DDIM + d] = acc;
    }
}

// ---------------- launch -----------------------------------------------------------
extern "C" void kernel_launch(void* const* d_in, const int* in_sizes, int n_in,
                              void* d_out, int out_size)
{
    const float* S1    = (const float*)d_in[0];
    const float* S2    = (const float*)d_in[1];
    const int*   mask1 = (const int*)  d_in[2];
    const int*   mask2 = (const int*)  d_in[3];
    const float* W     = (const float*)d_in[4];
    const float* Wv    = (const float*)d_in[5];
    const float* Wq    = (const float*)d_in[6];
    const float* w_hv  = (const float*)d_in[7];
    const float* w_hq  = (const float*)d_in[8];
    float* out = (float*)d_out;

    __nv_bfloat16 *S1h,*S1l,*S2h,*S2l,*Wth,*Wtl,*Wvth,*Wvtl,*Wqth,*Wqtl;
    __nv_bfloat16 *Th,*Tl,*Ch,*Cl,*CTh,*CTl,*Pth,*Ptl,*Qth,*Qtl;
    float *P,*Q,*Hv,*Hq;
    cudaGetSymbolAddress((void**)&S1h, g_S1h);  cudaGetSymbolAddress((void**)&S1l, g_S1l);
    cudaGetSymbolAddress((void**)&S2h, g_S2h);  cudaGetSymbolAddress((void**)&S2l, g_S2l);
    cudaGetSymbolAddress((void**)&Wth, g_Wth);  cudaGetSymbolAddress((void**)&Wtl, g_Wtl);
    cudaGetSymbolAddress((void**)&Wvth,g_Wvth); cudaGetSymbolAddress((void**)&Wvtl,g_Wvtl);
    cudaGetSymbolAddress((void**)&Wqth,g_Wqth); cudaGetSymbolAddress((void**)&Wqtl,g_Wqtl);
    cudaGetSymbolAddress((void**)&Th,  g_Th);   cudaGetSymbolAddress((void**)&Tl,  g_Tl);
    cudaGetSymbolAddress((void**)&Ch,  g_Ch);   cudaGetSymbolAddress((void**)&Cl,  g_Cl);
    cudaGetSymbolAddress((void**)&CTh, g_CTh);  cudaGetSymbolAddress((void**)&CTl, g_CTl);
    cudaGetSymbolAddress((void**)&Pth, g_Pth);  cudaGetSymbolAddress((void**)&Ptl, g_Ptl);
    cudaGetSymbolAddress((void**)&Qth, g_Qth);  cudaGetSymbolAddress((void**)&Qtl, g_Qtl);
    cudaGetSymbolAddress((void**)&P,   g_P);    cudaGetSymbolAddress((void**)&Q,   g_Q);
    cudaGetSymbolAddress((void**)&Hv,  g_Hv);   cudaGetSymbolAddress((void**)&Hq,  g_Hq);

    cudaFuncSetAttribute(mega123, cudaFuncAttributeMaxDynamicSharedMemorySize, SM_BYTES);
    cudaFuncSetAttribute(gemm4,   cudaFuncAttributeMaxDynamicSharedMemorySize, SM_BYTES);
    cudaFuncSetAttribute(mega56,  cudaFuncAttributeMaxDynamicSharedMemorySize, SM_BYTES);

    const dim3 blk(256);
    const size_t sLL = (size_t)LLEN * LLEN;
    const size_t sLA = (size_t)LLEN * AADIM;
    const size_t sLD = (size_t)LLEN * DDIM;
    const int n4 = BL * DDIM / 4;

    split_both<<<(2 * n4 + 255) / 256, blk>>>(
        (const float4*)S1, (uint2*)S1h, (uint2*)S1l,
        (const float4*)S2, (uint2*)S2h, (uint2*)S2l, n4);
    tsplit_all<<<512, blk>>>(W, Wth, Wtl, Wv, Wvth, Wvtl, Wq, Wqth, Wqtl);

    GArgs g1 = { S1h, S1l, Wth, Wtl, 0, 0, DDIM, DDIM,
                 nullptr, 0, 0,  nullptr, 0, 0,
                 Th, Tl, 0, DDIM,  nullptr, nullptr, 0, 0 };
    GArgs g2 = { S1h, S1l, Wvth, Wvtl, 0, 0, DDIM, DDIM,
                 nullptr, 0, 0,  P, 0, AADIM,
                 nullptr, nullptr, 0, 0,  Pth, Ptl, 0, BL };
    GArgs g3 = { S2h, S2l, Wqth, Wqtl, 0, 0, DDIM, DDIM,
                 nullptr, 0, 0,  Q, 0, AADIM,
                 nullptr, nullptr, 0, 0,  Qth, Qtl, 0, BL };
    mega123<<<dim3(BL/128, 1, 8), blk, SM_BYTES>>>(g1, g2, g3);

    GArgs g4 = { Th, Tl, S2h, S2l, sLD, sLD, DDIM, DDIM,
                 nullptr, 0, 0,  nullptr, 0, 0,
                 Ch, Cl, sLL, LLEN,  CTh, CTl, sLL, LLEN };
    gemm4<<<dim3(LLEN/128, LLEN/128, BBATCH), blk, SM_BYTES>>>(g4);

    GArgs g5 = { Ch, Cl, Qth, Qtl, sLL, (size_t)LLEN, LLEN, BL,
                 P, sLA, AADIM,  Hv, sLA, AADIM,
                 nullptr, nullptr, 0, 0,  nullptr, nullptr, 0, 0 };
    GArgs g6 = { CTh, CTl, Pth, Ptl, sLL, (size_t)LLEN, LLEN, BL,
                 Q, sLA, AADIM,  Hq, sLA, AADIM,
                 nullptr, nullptr, 0, 0,  nullptr, nullptr, 0, 0 };
    mega56<<<dim3(LLEN/128, AADIM/128, 128), blk, SM_BYTES>>>(g5, g6);

    attn_pool2<<<2 * BBATCH, blk>>>(Hv, w_hv, mask1, S1, Hq, w_hq, mask2, S2, out);
}